// round 5
// baseline (speedup 1.0000x reference)
#include <cuda_runtime.h>
#include <cuda_bf16.h>
#include <math.h>

// Problem constants
#define B_SZ 4
#define T_SZ 2048
#define D_SZ 1024
#define H_SZ 16
#define DK_SZ 64
#define D3 (3 * D_SZ)

// Scratch (device globals; no allocation allowed)
__device__ __align__(16) float g_qkv[(size_t)B_SZ * T_SZ * D3];    // 96 MB
__device__ __align__(16) float g_attn[(size_t)B_SZ * T_SZ * D_SZ]; // 32 MB
__device__ int g_prefix[B_SZ];

// ---------------------------------------------------------------------------
// Prefix decode: robust to the harness storing prefix_lengths as int32 or
// int64. Values are in [0, 1024). If stored as little-endian int64, the odd
// int32 words (hi halves) are all zero; if stored as int32, odd words are
// real prefix values (zero with prob ~1/1024 each).
// ---------------------------------------------------------------------------
__global__ void decode_prefix_kernel(const int* __restrict__ raw, int nelem) {
    // single thread
    bool is64 = (raw[1] == 0) && (raw[3] == 0);
    for (int b = 0; b < B_SZ; b++) {
        int p = is64 ? raw[2 * b] : raw[b];
        if (p < 0) p = 0;
        if (p > T_SZ) p = T_SZ;
        g_prefix[b] = p;
    }
}

// ---------------------------------------------------------------------------
// GEMM: C[M,N] = A[M,K] @ B[N,K]^T   (both row-major, K contiguous)
// Tiles: BM=64, BN=64, BK=16. 256 threads, each computes 4x4.
// ---------------------------------------------------------------------------
#define BM 64
#define BN 64
#define BK 16

__global__ __launch_bounds__(256)
void gemm_nt_kernel(const float* __restrict__ A, const float* __restrict__ Bm,
                    float* __restrict__ C, int M, int N, int K) {
    __shared__ float As[BK][BM];
    __shared__ float Bs[BK][BN];

    const int tid = threadIdx.x;
    const int row0 = blockIdx.y * BM;
    const int col0 = blockIdx.x * BN;

    const int tx = tid & 15;   // 0..15
    const int ty = tid >> 4;   // 0..15

    const int lr = tid >> 2;          // 0..63 (row within tile)
    const int lk = (tid & 3) * 4;     // 0,4,8,12

    float acc[4][4];
#pragma unroll
    for (int i = 0; i < 4; i++)
#pragma unroll
        for (int j = 0; j < 4; j++) acc[i][j] = 0.0f;

    for (int k0 = 0; k0 < K; k0 += BK) {
        float4 a4 = *(const float4*)(A + (size_t)(row0 + lr) * K + k0 + lk);
        float4 b4 = *(const float4*)(Bm + (size_t)(col0 + lr) * K + k0 + lk);
        As[lk + 0][lr] = a4.x; As[lk + 1][lr] = a4.y;
        As[lk + 2][lr] = a4.z; As[lk + 3][lr] = a4.w;
        Bs[lk + 0][lr] = b4.x; Bs[lk + 1][lr] = b4.y;
        Bs[lk + 2][lr] = b4.z; Bs[lk + 3][lr] = b4.w;
        __syncthreads();

#pragma unroll
        for (int kk = 0; kk < BK; kk++) {
            float4 ar = *(const float4*)&As[kk][ty * 4];
            float4 br = *(const float4*)&Bs[kk][tx * 4];
            float a[4] = {ar.x, ar.y, ar.z, ar.w};
            float b[4] = {br.x, br.y, br.z, br.w};
#pragma unroll
            for (int i = 0; i < 4; i++)
#pragma unroll
                for (int j = 0; j < 4; j++)
                    acc[i][j] = fmaf(a[i], b[j], acc[i][j]);
        }
        __syncthreads();
    }

#pragma unroll
    for (int i = 0; i < 4; i++) {
        float4 v = make_float4(acc[i][0], acc[i][1], acc[i][2], acc[i][3]);
        *(float4*)(C + (size_t)(row0 + ty * 4 + i) * N + col0 + tx * 4) = v;
    }
}

// ---------------------------------------------------------------------------
// Flash-style attention with prefix-LM mask.
// qkv layout per token row (3*D floats): [s(0..2)][h][dk]
// One thread per query row; block = 128 queries for one (b,h).
// allowed(q,k) = (k < P) || (q >= P && k <= q)
// ---------------------------------------------------------------------------
#define TQ 128
#define TK 64

__global__ __launch_bounds__(TQ)
void attn_kernel(const float* __restrict__ qkv,
                 float* __restrict__ out) {
    __shared__ float Ks[TK][DK_SZ];
    __shared__ float Vs[TK][DK_SZ];

    const int b = blockIdx.z;
    const int h = blockIdx.y;
    const int q0 = blockIdx.x * TQ;
    const int q = q0 + threadIdx.x;

    const int P = g_prefix[b];
    const float scale = 0.125f;  // 1/sqrt(64)

    float qr[DK_SZ];
    {
        const float* qrow = qkv + (size_t)(b * T_SZ + q) * D3 + h * DK_SZ;
#pragma unroll
        for (int i = 0; i < DK_SZ / 4; i++) {
            float4 t = *(const float4*)(qrow + 4 * i);
            qr[4 * i + 0] = t.x; qr[4 * i + 1] = t.y;
            qr[4 * i + 2] = t.z; qr[4 * i + 3] = t.w;
        }
    }

    float m = -1e30f;
    float l = 0.0f;
    float acc[DK_SZ];
#pragma unroll
    for (int d = 0; d < DK_SZ; d++) acc[d] = 0.0f;

    int kend = q0 + TQ;
    if (P > kend) kend = P;
    if (kend > T_SZ) kend = T_SZ;

    for (int kt = 0; kt < kend; kt += TK) {
        for (int e = threadIdx.x; e < TK * (DK_SZ / 4); e += TQ) {
            int r = e >> 4;          // 0..63
            int c4 = (e & 15) * 4;   // 0..60
            const float* base = qkv + (size_t)(b * T_SZ + kt + r) * D3 + h * DK_SZ;
            *(float4*)&Ks[r][c4] = *(const float4*)(base + D_SZ + c4);
            *(float4*)&Vs[r][c4] = *(const float4*)(base + 2 * D_SZ + c4);
        }
        __syncthreads();

        const int jend = (kend - kt) < TK ? (kend - kt) : TK;
        for (int j = 0; j < jend; j++) {
            const int k = kt + j;
            const bool allowed = (k < P) || (q >= P && k <= q);
            if (!allowed) continue;

            float s0 = 0.f, s1 = 0.f, s2 = 0.f, s3 = 0.f;
#pragma unroll
            for (int d = 0; d < DK_SZ; d += 4) {
                s0 = fmaf(qr[d + 0], Ks[j][d + 0], s0);
                s1 = fmaf(qr[d + 1], Ks[j][d + 1], s1);
                s2 = fmaf(qr[d + 2], Ks[j][d + 2], s2);
                s3 = fmaf(qr[d + 3], Ks[j][d + 3], s3);
            }
            float s = ((s0 + s1) + (s2 + s3)) * scale;

            float mnew = fmaxf(m, s);
            float p = __expf(s - mnew);
            if (mnew > m) {
                float corr = __expf(m - mnew);
                l = l * corr + p;
#pragma unroll
                for (int d = 0; d < DK_SZ; d++)
                    acc[d] = fmaf(acc[d], corr, p * Vs[j][d]);
                m = mnew;
            } else {
                l += p;
#pragma unroll
                for (int d = 0; d < DK_SZ; d++)
                    acc[d] = fmaf(p, Vs[j][d], acc[d]);
            }
        }
        __syncthreads();
    }

    const float inv = 1.0f / l;
    float* orow = out + (size_t)(b * T_SZ + q) * D_SZ + h * DK_SZ;
#pragma unroll
    for (int i = 0; i < DK_SZ / 4; i++) {
        float4 t;
        t.x = acc[4 * i + 0] * inv; t.y = acc[4 * i + 1] * inv;
        t.z = acc[4 * i + 2] * inv; t.w = acc[4 * i + 3] * inv;
        *(float4*)(orow + 4 * i) = t;
    }
}

// ---------------------------------------------------------------------------
// launch
// inputs: d_in[0]=x fp32 [B,T,D], d_in[1]=prefix_lengths (int32 or int64) [B],
//         d_in[2]=W_qkv fp32 [3D,D], d_in[3]=W_o fp32 [D,D]
// output: fp32 [B,T,D]
// ---------------------------------------------------------------------------
extern "C" void kernel_launch(void* const* d_in, const int* in_sizes, int n_in,
                              void* d_out, int out_size) {
    const float* x = (const float*)d_in[0];
    const int* prefix_raw = (const int*)d_in[1];
    const float* W_qkv = (const float*)d_in[2];
    const float* W_o = (const float*)d_in[3];
    float* out = (float*)d_out;

    float* qkv = nullptr;
    float* attn = nullptr;
    cudaGetSymbolAddress((void**)&qkv, g_qkv);
    cudaGetSymbolAddress((void**)&attn, g_attn);

    const int M = B_SZ * T_SZ;  // 8192

    // 0) decode prefix lengths (dtype-robust)
    decode_prefix_kernel<<<1, 1>>>(prefix_raw, in_sizes[1]);

    // 1) qkv = x @ W_qkv^T   [8192, 3072]
    {
        dim3 grid(D3 / BN, M / BM);
        gemm_nt_kernel<<<grid, 256>>>(x, W_qkv, qkv, M, D3, D_SZ);
    }

    // 2) attention -> attn [8192, 1024] (already in (b,t,h*dk) layout)
    {
        dim3 grid(T_SZ / TQ, H_SZ, B_SZ);
        attn_kernel<<<grid, TQ>>>(qkv, attn);
    }

    // 3) out = attn @ W_o^T  [8192, 1024]
    {
        dim3 grid(D_SZ / BN, M / BM);
        gemm_nt_kernel<<<grid, 256>>>(attn, W_o, out, M, D_SZ, D_SZ);
    }
}

// round 6
// speedup vs baseline: 2.4047x; 2.4047x over previous
#include <cuda_runtime.h>
#include <cuda_bf16.h>
#include <math.h>

// Problem constants
#define B_SZ 4
#define T_SZ 2048
#define D_SZ 1024
#define H_SZ 16
#define DK_SZ 64
#define D3 (3 * D_SZ)

// Scratch (device globals; no allocation allowed)
__device__ __align__(16) float g_qkv[(size_t)B_SZ * T_SZ * D3];    // 96 MB
__device__ __align__(16) float g_attn[(size_t)B_SZ * T_SZ * D_SZ]; // 32 MB
__device__ int g_prefix[B_SZ];

// ---------------------------------------------------------------------------
// Prefix decode (robust to int32 or int64 storage).
// ---------------------------------------------------------------------------
__global__ void decode_prefix_kernel(const int* __restrict__ raw) {
    bool is64 = (raw[1] == 0) && (raw[3] == 0);
    for (int b = 0; b < B_SZ; b++) {
        int p = is64 ? raw[2 * b] : raw[b];
        if (p < 0) p = 0;
        if (p > T_SZ) p = T_SZ;
        g_prefix[b] = p;
    }
}

// ---------------------------------------------------------------------------
// TF32 tensor-core GEMM: C[M,N] = A[M,K] @ W[N,K]^T  (row-major, K contig)
// BM=128, BN=128, BK=16, 256 threads = 8 warps (2x4), warp tile 64x32.
// mma.sync.aligned.m16n8k8.row.col.f32.tf32.tf32.f32
// Smem holds operands PRE-PERMUTED into mma fragment layout:
//   A frag (thread=lane): a0=(r,c) a1=(r+8,c) a2=(r,c+4) a3=(r+8,c+4),
//     r=lane/4, c=lane%4  -> slot = row_hi + 2*col_hi
//   B frag: b0=(k=lane%4, n=lane/4), b1=(k+4, n)         -> slot = k_hi
// so fragment loads are one LDS.128 (A) / LDS.64 (B), conflict-free.
// ---------------------------------------------------------------------------
#define TBM 128
#define TBN 128
#define TBK 16

__device__ __forceinline__ unsigned f2tf32(float v) {
    unsigned u;
    asm("cvt.rna.tf32.f32 %0, %1;" : "=r"(u) : "f"(v));
    return u;
}

__device__ __forceinline__ void mma_tf32(float* c, const uint4& a, const uint2& b) {
    asm volatile(
        "mma.sync.aligned.m16n8k8.row.col.f32.tf32.tf32.f32 "
        "{%0,%1,%2,%3}, {%4,%5,%6,%7}, {%8,%9}, {%0,%1,%2,%3};"
        : "+f"(c[0]), "+f"(c[1]), "+f"(c[2]), "+f"(c[3])
        : "r"(a.x), "r"(a.y), "r"(a.z), "r"(a.w), "r"(b.x), "r"(b.y));
}

__global__ __launch_bounds__(256)
void gemm_tf32_nt(const float* __restrict__ A, const float* __restrict__ W,
                  float* __restrict__ C, int M, int N, int K) {
    // [buf][kstep][mtile][lane][slot]
    __shared__ unsigned As[2][2][8][32][4];   // 16 KB
    __shared__ unsigned Bs[2][2][16][32][2];  // 16 KB

    const int tid = threadIdx.x;
    const int warp = tid >> 5;
    const int lane = tid & 31;
    const int wm = warp >> 2;   // 0..1 -> m offset wm*64
    const int wn = warp & 3;    // 0..3 -> n offset wn*32

    const int row0 = blockIdx.y * TBM;
    const int col0 = blockIdx.x * TBN;

    // gmem load mapping: thread t -> row lr = t/2, kstep lks = t%2 (8 k each)
    const int lr = tid >> 1;
    const int lks = tid & 1;
    const float* Aptr = A + (size_t)(row0 + lr) * K + lks * 8;
    const float* Wptr = W + (size_t)(col0 + lr) * K + lks * 8;

    // permuted-store indices for this thread's values
    const int plane = (lr & 7) * 4;       // lane' base; +e for element e
    const int mt_ld = lr >> 4;            // A mtile
    const int arow_hi = (lr >> 3) & 1;    // A slot row_hi bit
    const int nt_ld = lr >> 3;            // B ntile

    float acc[4][4][4];
#pragma unroll
    for (int i = 0; i < 4; i++)
#pragma unroll
        for (int j = 0; j < 4; j++)
#pragma unroll
            for (int c = 0; c < 4; c++) acc[i][j][c] = 0.0f;

    // prologue: load + store tile 0
    float4 a0 = *(const float4*)(Aptr);
    float4 a1 = *(const float4*)(Aptr + 4);
    float4 b0 = *(const float4*)(Wptr);
    float4 b1 = *(const float4*)(Wptr + 4);

    int buf = 0;
    {
        // A: a0 -> col_hi=0 (slot arow_hi), a1 -> col_hi=1 (slot arow_hi+2)
        As[buf][lks][mt_ld][plane + 0][arow_hi]     = f2tf32(a0.x);
        As[buf][lks][mt_ld][plane + 1][arow_hi]     = f2tf32(a0.y);
        As[buf][lks][mt_ld][plane + 2][arow_hi]     = f2tf32(a0.z);
        As[buf][lks][mt_ld][plane + 3][arow_hi]     = f2tf32(a0.w);
        As[buf][lks][mt_ld][plane + 0][arow_hi + 2] = f2tf32(a1.x);
        As[buf][lks][mt_ld][plane + 1][arow_hi + 2] = f2tf32(a1.y);
        As[buf][lks][mt_ld][plane + 2][arow_hi + 2] = f2tf32(a1.z);
        As[buf][lks][mt_ld][plane + 3][arow_hi + 2] = f2tf32(a1.w);
        // B: b0 -> k_hi=0 (slot 0), b1 -> k_hi=1 (slot 1)
        Bs[buf][lks][nt_ld][plane + 0][0] = f2tf32(b0.x);
        Bs[buf][lks][nt_ld][plane + 1][0] = f2tf32(b0.y);
        Bs[buf][lks][nt_ld][plane + 2][0] = f2tf32(b0.z);
        Bs[buf][lks][nt_ld][plane + 3][0] = f2tf32(b0.w);
        Bs[buf][lks][nt_ld][plane + 0][1] = f2tf32(b1.x);
        Bs[buf][lks][nt_ld][plane + 1][1] = f2tf32(b1.y);
        Bs[buf][lks][nt_ld][plane + 2][1] = f2tf32(b1.z);
        Bs[buf][lks][nt_ld][plane + 3][1] = f2tf32(b1.w);
    }
    __syncthreads();

    const int nIter = K / TBK;
    for (int it = 0; it < nIter; it++) {
        float4 na0, na1, nb0, nb1;
        const bool pre = (it + 1 < nIter);
        if (pre) {
            const float* ap = Aptr + (size_t)(it + 1) * TBK;
            const float* wp = Wptr + (size_t)(it + 1) * TBK;
            na0 = *(const float4*)(ap);
            na1 = *(const float4*)(ap + 4);
            nb0 = *(const float4*)(wp);
            nb1 = *(const float4*)(wp + 4);
        }

#pragma unroll
        for (int ks = 0; ks < 2; ks++) {
            uint4 af[4];
            uint2 bf[4];
#pragma unroll
            for (int mt = 0; mt < 4; mt++)
                af[mt] = *reinterpret_cast<const uint4*>(&As[buf][ks][wm * 4 + mt][lane][0]);
#pragma unroll
            for (int nt = 0; nt < 4; nt++)
                bf[nt] = *reinterpret_cast<const uint2*>(&Bs[buf][ks][wn * 4 + nt][lane][0]);
#pragma unroll
            for (int mt = 0; mt < 4; mt++)
#pragma unroll
                for (int nt = 0; nt < 4; nt++)
                    mma_tf32(acc[mt][nt], af[mt], bf[nt]);
        }

        if (pre) {
            int nb = buf ^ 1;
            As[nb][lks][mt_ld][plane + 0][arow_hi]     = f2tf32(na0.x);
            As[nb][lks][mt_ld][plane + 1][arow_hi]     = f2tf32(na0.y);
            As[nb][lks][mt_ld][plane + 2][arow_hi]     = f2tf32(na0.z);
            As[nb][lks][mt_ld][plane + 3][arow_hi]     = f2tf32(na0.w);
            As[nb][lks][mt_ld][plane + 0][arow_hi + 2] = f2tf32(na1.x);
            As[nb][lks][mt_ld][plane + 1][arow_hi + 2] = f2tf32(na1.y);
            As[nb][lks][mt_ld][plane + 2][arow_hi + 2] = f2tf32(na1.z);
            As[nb][lks][mt_ld][plane + 3][arow_hi + 2] = f2tf32(na1.w);
            Bs[nb][lks][nt_ld][plane + 0][0] = f2tf32(nb0.x);
            Bs[nb][lks][nt_ld][plane + 1][0] = f2tf32(nb0.y);
            Bs[nb][lks][nt_ld][plane + 2][0] = f2tf32(nb0.z);
            Bs[nb][lks][nt_ld][plane + 3][0] = f2tf32(nb0.w);
            Bs[nb][lks][nt_ld][plane + 0][1] = f2tf32(nb1.x);
            Bs[nb][lks][nt_ld][plane + 1][1] = f2tf32(nb1.y);
            Bs[nb][lks][nt_ld][plane + 2][1] = f2tf32(nb1.z);
            Bs[nb][lks][nt_ld][plane + 3][1] = f2tf32(nb1.w);
            __syncthreads();
            buf = nb;
        }
    }

    // epilogue: c0=(r,c) c1=(r,c+1) c2=(r+8,c) c3=(r+8,c+1), r=lane/4, c=(lane%4)*2
    const int r_base = row0 + wm * 64 + (lane >> 2);
    const int c_base = col0 + wn * 32 + (lane & 3) * 2;
#pragma unroll
    for (int mt = 0; mt < 4; mt++) {
#pragma unroll
        for (int nt = 0; nt < 4; nt++) {
            int r = r_base + mt * 16;
            int c = c_base + nt * 8;
            *(float2*)&C[(size_t)r * N + c] =
                make_float2(acc[mt][nt][0], acc[mt][nt][1]);
            *(float2*)&C[(size_t)(r + 8) * N + c] =
                make_float2(acc[mt][nt][2], acc[mt][nt][3]);
        }
    }
}

// ---------------------------------------------------------------------------
// Flash attention, prefix-LM mask folded into loop bounds:
//   allowed(q,k)  <=>  k < myend,  myend = (q < P) ? P : q+1
// One thread per query; float4 smem traffic throughout.
// ---------------------------------------------------------------------------
#define TQ 128
#define TK 64

__device__ __forceinline__ float4 f4ma(const float4 a, const float4 b, float4 c) {
    c.x = fmaf(a.x, b.x, c.x);
    c.y = fmaf(a.y, b.y, c.y);
    c.z = fmaf(a.z, b.z, c.z);
    c.w = fmaf(a.w, b.w, c.w);
    return c;
}
__device__ __forceinline__ float4 f4mas(const float s, const float4 b, float4 c) {
    c.x = fmaf(s, b.x, c.x);
    c.y = fmaf(s, b.y, c.y);
    c.z = fmaf(s, b.z, c.z);
    c.w = fmaf(s, b.w, c.w);
    return c;
}

__global__ __launch_bounds__(TQ)
void attn_kernel(const float* __restrict__ qkv, float* __restrict__ out) {
    __shared__ float Ks[TK][DK_SZ];
    __shared__ float Vs[TK][DK_SZ];

    const int b = blockIdx.z;
    const int h = blockIdx.y;
    const int q0 = blockIdx.x * TQ;
    const int q = q0 + threadIdx.x;

    const int P = g_prefix[b];
    const int myend = (q < P) ? P : (q + 1);   // exclusive end of allowed keys

    float4 qr[16];
    {
        const float4* qrow =
            (const float4*)(qkv + (size_t)(b * T_SZ + q) * D3 + h * DK_SZ);
#pragma unroll
        for (int i = 0; i < 16; i++) qr[i] = qrow[i];
    }

    float m = -1e30f, l = 0.0f;
    float4 acc[16];
#pragma unroll
    for (int i = 0; i < 16; i++) acc[i] = make_float4(0.f, 0.f, 0.f, 0.f);

    int kend = q0 + TQ;
    if (P > kend) kend = P;
    if (kend > T_SZ) kend = T_SZ;

    for (int kt = 0; kt < kend; kt += TK) {
        for (int e = threadIdx.x; e < TK * 16; e += TQ) {
            int r = e >> 4;
            int c4 = e & 15;
            const float* base = qkv + (size_t)(b * T_SZ + kt + r) * D3 + h * DK_SZ;
            ((float4*)Ks[r])[c4] = ((const float4*)(base + D_SZ))[c4];
            ((float4*)Vs[r])[c4] = ((const float4*)(base + 2 * D_SZ))[c4];
        }
        __syncthreads();

        int jcnt = kend - kt;
        if (jcnt > TK) jcnt = TK;
        {
            int je = myend - kt;
            if (je < jcnt) jcnt = je;
        }

        for (int j = 0; j < jcnt; j++) {
            const float4* K4 = (const float4*)Ks[j];
            float4 p0 = make_float4(0.f, 0.f, 0.f, 0.f), p1 = p0, p2 = p0, p3 = p0;
#pragma unroll
            for (int i = 0; i < 16; i += 4) {
                p0 = f4ma(qr[i + 0], K4[i + 0], p0);
                p1 = f4ma(qr[i + 1], K4[i + 1], p1);
                p2 = f4ma(qr[i + 2], K4[i + 2], p2);
                p3 = f4ma(qr[i + 3], K4[i + 3], p3);
            }
            float s = ((p0.x + p0.y) + (p0.z + p0.w)) + ((p1.x + p1.y) + (p1.z + p1.w)) +
                      ((p2.x + p2.y) + (p2.z + p2.w)) + ((p3.x + p3.y) + (p3.z + p3.w));
            s *= 0.125f;  // 1/sqrt(64)

            const float4* V4 = (const float4*)Vs[j];
            float mnew = fmaxf(m, s);
            float p = __expf(s - mnew);
            if (mnew > m) {
                float corr = __expf(m - mnew);
                l = l * corr + p;
#pragma unroll
                for (int i = 0; i < 16; i++) {
                    float4 a = acc[i], v = V4[i];
                    a.x = fmaf(a.x, corr, p * v.x);
                    a.y = fmaf(a.y, corr, p * v.y);
                    a.z = fmaf(a.z, corr, p * v.z);
                    a.w = fmaf(a.w, corr, p * v.w);
                    acc[i] = a;
                }
                m = mnew;
            } else {
                l += p;
#pragma unroll
                for (int i = 0; i < 16; i++) acc[i] = f4mas(p, V4[i], acc[i]);
            }
        }
        __syncthreads();
    }

    const float inv = 1.0f / l;
    float4* orow = (float4*)(out + (size_t)(b * T_SZ + q) * D_SZ + h * DK_SZ);
#pragma unroll
    for (int i = 0; i < 16; i++) {
        float4 a = acc[i];
        orow[i] = make_float4(a.x * inv, a.y * inv, a.z * inv, a.w * inv);
    }
}

// ---------------------------------------------------------------------------
// launch
// ---------------------------------------------------------------------------
extern "C" void kernel_launch(void* const* d_in, const int* in_sizes, int n_in,
                              void* d_out, int out_size) {
    const float* x = (const float*)d_in[0];
    const int* prefix_raw = (const int*)d_in[1];
    const float* W_qkv = (const float*)d_in[2];
    const float* W_o = (const float*)d_in[3];
    float* out = (float*)d_out;

    float* qkv = nullptr;
    float* attn = nullptr;
    cudaGetSymbolAddress((void**)&qkv, g_qkv);
    cudaGetSymbolAddress((void**)&attn, g_attn);

    const int M = B_SZ * T_SZ;  // 8192

    decode_prefix_kernel<<<1, 1>>>(prefix_raw);

    // 1) qkv = x @ W_qkv^T   [8192, 3072]
    {
        dim3 grid(D3 / TBN, M / TBM);
        gemm_tf32_nt<<<grid, 256>>>(x, W_qkv, qkv, M, D3, D_SZ);
    }

    // 2) attention -> attn [8192, 1024]
    {
        dim3 grid(T_SZ / TQ, H_SZ, B_SZ);
        attn_kernel<<<grid, TQ>>>(qkv, attn);
    }

    // 3) out = attn @ W_o^T  [8192, 1024]
    {
        dim3 grid(D_SZ / TBN, M / TBM);
        gemm_tf32_nt<<<grid, 256>>>(attn, W_o, out, M, D_SZ, D_SZ);
    }
}

// round 7
// speedup vs baseline: 4.2254x; 1.7572x over previous
#include <cuda_runtime.h>
#include <cuda_bf16.h>
#include <math.h>

// Problem constants
#define B_SZ 4
#define T_SZ 2048
#define D_SZ 1024
#define H_SZ 16
#define DK_SZ 64
#define D3 (3 * D_SZ)

// Scratch (device globals; no allocation allowed)
__device__ __align__(16) float g_qkv[(size_t)B_SZ * T_SZ * D3];    // 96 MB
__device__ __align__(16) float g_attn[(size_t)B_SZ * T_SZ * D_SZ]; // 32 MB
__device__ int g_prefix[B_SZ];

// ---------------------------------------------------------------------------
// Prefix decode (robust to int32 or int64 storage).
// ---------------------------------------------------------------------------
__global__ void decode_prefix_kernel(const int* __restrict__ raw) {
    bool is64 = (raw[1] == 0) && (raw[3] == 0);
    for (int b = 0; b < B_SZ; b++) {
        int p = is64 ? raw[2 * b] : raw[b];
        if (p < 0) p = 0;
        if (p > T_SZ) p = T_SZ;
        g_prefix[b] = p;
    }
}

// ---------------------------------------------------------------------------
// Common tf32 mma helpers
// ---------------------------------------------------------------------------
__device__ __forceinline__ unsigned f2tf32(float v) {
    unsigned u;
    asm("cvt.rna.tf32.f32 %0, %1;" : "=r"(u) : "f"(v));
    return u;
}

__device__ __forceinline__ void mma_tf32(float* c, const uint4& a, const uint2& b) {
    asm volatile(
        "mma.sync.aligned.m16n8k8.row.col.f32.tf32.tf32.f32 "
        "{%0,%1,%2,%3}, {%4,%5,%6,%7}, {%8,%9}, {%0,%1,%2,%3};"
        : "+f"(c[0]), "+f"(c[1]), "+f"(c[2]), "+f"(c[3])
        : "r"(a.x), "r"(a.y), "r"(a.z), "r"(a.w), "r"(b.x), "r"(b.y));
}

// ---------------------------------------------------------------------------
// TF32 tensor-core GEMM: C[M,N] = A[M,K] @ W[N,K]^T  (row-major, K contig)
// BM=128, BN=128, BK=16, 256 threads = 8 warps (2x4), warp tile 64x32.
// ---------------------------------------------------------------------------
#define TBM 128
#define TBN 128
#define TBK 16

__global__ __launch_bounds__(256)
void gemm_tf32_nt(const float* __restrict__ A, const float* __restrict__ W,
                  float* __restrict__ C, int M, int N, int K) {
    __shared__ unsigned As[2][2][8][32][4];   // 16 KB
    __shared__ unsigned Bs[2][2][16][32][2];  // 16 KB

    const int tid = threadIdx.x;
    const int warp = tid >> 5;
    const int lane = tid & 31;
    const int wm = warp >> 2;
    const int wn = warp & 3;

    const int row0 = blockIdx.y * TBM;
    const int col0 = blockIdx.x * TBN;

    const int lr = tid >> 1;
    const int lks = tid & 1;
    const float* Aptr = A + (size_t)(row0 + lr) * K + lks * 8;
    const float* Wptr = W + (size_t)(col0 + lr) * K + lks * 8;

    const int plane = (lr & 7) * 4;
    const int mt_ld = lr >> 4;
    const int arow_hi = (lr >> 3) & 1;
    const int nt_ld = lr >> 3;

    float acc[4][4][4];
#pragma unroll
    for (int i = 0; i < 4; i++)
#pragma unroll
        for (int j = 0; j < 4; j++)
#pragma unroll
            for (int c = 0; c < 4; c++) acc[i][j][c] = 0.0f;

    float4 a0 = *(const float4*)(Aptr);
    float4 a1 = *(const float4*)(Aptr + 4);
    float4 b0 = *(const float4*)(Wptr);
    float4 b1 = *(const float4*)(Wptr + 4);

    int buf = 0;
    {
        As[buf][lks][mt_ld][plane + 0][arow_hi]     = f2tf32(a0.x);
        As[buf][lks][mt_ld][plane + 1][arow_hi]     = f2tf32(a0.y);
        As[buf][lks][mt_ld][plane + 2][arow_hi]     = f2tf32(a0.z);
        As[buf][lks][mt_ld][plane + 3][arow_hi]     = f2tf32(a0.w);
        As[buf][lks][mt_ld][plane + 0][arow_hi + 2] = f2tf32(a1.x);
        As[buf][lks][mt_ld][plane + 1][arow_hi + 2] = f2tf32(a1.y);
        As[buf][lks][mt_ld][plane + 2][arow_hi + 2] = f2tf32(a1.z);
        As[buf][lks][mt_ld][plane + 3][arow_hi + 2] = f2tf32(a1.w);
        Bs[buf][lks][nt_ld][plane + 0][0] = f2tf32(b0.x);
        Bs[buf][lks][nt_ld][plane + 1][0] = f2tf32(b0.y);
        Bs[buf][lks][nt_ld][plane + 2][0] = f2tf32(b0.z);
        Bs[buf][lks][nt_ld][plane + 3][0] = f2tf32(b0.w);
        Bs[buf][lks][nt_ld][plane + 0][1] = f2tf32(b1.x);
        Bs[buf][lks][nt_ld][plane + 1][1] = f2tf32(b1.y);
        Bs[buf][lks][nt_ld][plane + 2][1] = f2tf32(b1.z);
        Bs[buf][lks][nt_ld][plane + 3][1] = f2tf32(b1.w);
    }
    __syncthreads();

    const int nIter = K / TBK;
    for (int it = 0; it < nIter; it++) {
        float4 na0, na1, nb0, nb1;
        const bool pre = (it + 1 < nIter);
        if (pre) {
            const float* ap = Aptr + (size_t)(it + 1) * TBK;
            const float* wp = Wptr + (size_t)(it + 1) * TBK;
            na0 = *(const float4*)(ap);
            na1 = *(const float4*)(ap + 4);
            nb0 = *(const float4*)(wp);
            nb1 = *(const float4*)(wp + 4);
        }

#pragma unroll
        for (int ks = 0; ks < 2; ks++) {
            uint4 af[4];
            uint2 bf[4];
#pragma unroll
            for (int mt = 0; mt < 4; mt++)
                af[mt] = *reinterpret_cast<const uint4*>(&As[buf][ks][wm * 4 + mt][lane][0]);
#pragma unroll
            for (int nt = 0; nt < 4; nt++)
                bf[nt] = *reinterpret_cast<const uint2*>(&Bs[buf][ks][wn * 4 + nt][lane][0]);
#pragma unroll
            for (int mt = 0; mt < 4; mt++)
#pragma unroll
                for (int nt = 0; nt < 4; nt++)
                    mma_tf32(acc[mt][nt], af[mt], bf[nt]);
        }

        if (pre) {
            int nb = buf ^ 1;
            As[nb][lks][mt_ld][plane + 0][arow_hi]     = f2tf32(na0.x);
            As[nb][lks][mt_ld][plane + 1][arow_hi]     = f2tf32(na0.y);
            As[nb][lks][mt_ld][plane + 2][arow_hi]     = f2tf32(na0.z);
            As[nb][lks][mt_ld][plane + 3][arow_hi]     = f2tf32(na0.w);
            As[nb][lks][mt_ld][plane + 0][arow_hi + 2] = f2tf32(na1.x);
            As[nb][lks][mt_ld][plane + 1][arow_hi + 2] = f2tf32(na1.y);
            As[nb][lks][mt_ld][plane + 2][arow_hi + 2] = f2tf32(na1.z);
            As[nb][lks][mt_ld][plane + 3][arow_hi + 2] = f2tf32(na1.w);
            Bs[nb][lks][nt_ld][plane + 0][0] = f2tf32(nb0.x);
            Bs[nb][lks][nt_ld][plane + 1][0] = f2tf32(nb0.y);
            Bs[nb][lks][nt_ld][plane + 2][0] = f2tf32(nb0.z);
            Bs[nb][lks][nt_ld][plane + 3][0] = f2tf32(nb0.w);
            Bs[nb][lks][nt_ld][plane + 0][1] = f2tf32(nb1.x);
            Bs[nb][lks][nt_ld][plane + 1][1] = f2tf32(nb1.y);
            Bs[nb][lks][nt_ld][plane + 2][1] = f2tf32(nb1.z);
            Bs[nb][lks][nt_ld][plane + 3][1] = f2tf32(nb1.w);
            __syncthreads();
            buf = nb;
        }
    }

    const int r_base = row0 + wm * 64 + (lane >> 2);
    const int c_base = col0 + wn * 32 + (lane & 3) * 2;
#pragma unroll
    for (int mt = 0; mt < 4; mt++) {
#pragma unroll
        for (int nt = 0; nt < 4; nt++) {
            int r = r_base + mt * 16;
            int c = c_base + nt * 8;
            *(float2*)&C[(size_t)r * N + c] =
                make_float2(acc[mt][nt][0], acc[mt][nt][1]);
            *(float2*)&C[(size_t)(r + 8) * N + c] =
                make_float2(acc[mt][nt][2], acc[mt][nt][3]);
        }
    }
}

// ---------------------------------------------------------------------------
// Tensor-core flash attention (prefix-LM mask).
// Block: 128 threads = 4 warps; 64 queries per block (16 per warp), one (b,h).
// K tiles of 64 keys. S = Q@K^T and O += P@V both via m16n8k8 tf32 mma.
//
// Fragment layouts (m16n8k8 tf32):
//   A: a0=(r,c) a1=(r+8,c) a2=(r,c+4) a3=(r+8,c+4), r=lane/4, c=lane%4
//   B: b0=(k=lane%4, n=lane/4), b1=(k+4, n)
//   C: c0=(r,2c) c1=(r,2c+1) c2=(r+8,2c) c3=(r+8,2c+1)
//
// P@V trick: A-frag of P built from S C-frag by register remap {c0,c2,c1,c3};
// mma k-index kk then corresponds to physical key psi(kk)=[0,2,4,6,1,3,5,7],
// so V rows are stored permuted by psi^-1(j)= ((j&1)<<2)|((j&7)>>1).
// ---------------------------------------------------------------------------
#define AT_TQ 64
#define AT_TK 64

__global__ __launch_bounds__(128)
void attn_mma_kernel(const float* __restrict__ qkv, float* __restrict__ out) {
    // Ks[dkstep][keytile][lane][slot] : B-frag layout for S = Q@K^T
    // Vs[keystep][dktile][lane][slot] : B-frag layout (key-permuted) for P@V
    __shared__ unsigned Ks[8][8][32][2];  // 16 KB
    __shared__ unsigned Vs[8][8][32][2];  // 16 KB

    const int b = blockIdx.z;
    const int h = blockIdx.y;
    const int q0 = blockIdx.x * AT_TQ;
    const int tid = threadIdx.x;
    const int warp = tid >> 5;
    const int lane = tid & 31;

    const int P = g_prefix[b];

    const int q0w = q0 + warp * 16;
    const int qa = q0w + (lane >> 2);
    const int qb = qa + 8;
    const int enda = (qa < P) ? P : (qa + 1);  // exclusive allowed-key end
    const int endb = (qb < P) ? P : (qb + 1);
    const int min_end_w = (q0w < P) ? P : (q0w + 1);

    int kend_w = q0w + 16;
    if (P > kend_w) kend_w = P;
    if (kend_w > T_SZ) kend_w = T_SZ;
    int kend = q0 + AT_TQ;
    if (P > kend) kend = P;
    if (kend > T_SZ) kend = T_SZ;

    // Q fragments, scale 1/sqrt(64)=0.125 folded in
    uint4 aq[8];
    {
        const float* qrA = qkv + (size_t)(b * T_SZ + qa) * D3 + h * DK_SZ;
        const float* qrB = qkv + (size_t)(b * T_SZ + qb) * D3 + h * DK_SZ;
        const int c = lane & 3;
#pragma unroll
        for (int g = 0; g < 8; g++) {
            aq[g].x = f2tf32(qrA[g * 8 + c] * 0.125f);
            aq[g].y = f2tf32(qrB[g * 8 + c] * 0.125f);
            aq[g].z = f2tf32(qrA[g * 8 + c + 4] * 0.125f);
            aq[g].w = f2tf32(qrB[g * 8 + c + 4] * 0.125f);
        }
    }

    float oacc[8][4];
#pragma unroll
    for (int dt = 0; dt < 8; dt++)
#pragma unroll
        for (int e = 0; e < 4; e++) oacc[dt][e] = 0.0f;
    float m0 = -1e30f, m1 = -1e30f, l0 = 0.0f, l1 = 0.0f;

    for (int kt = 0; kt < kend; kt += AT_TK) {
        // ---- load K tile into fragment layout (each thread: 4 chunks of 8 dk)
#pragma unroll
        for (int cc = 0; cc < 4; cc++) {
            int c = tid + cc * 128;         // 0..511
            int j = c & 63;                 // key within tile
            int ds = c >> 6;                // dk step
            const float* kr = qkv + (size_t)(b * T_SZ + kt + j) * D3 + D_SZ + h * DK_SZ + ds * 8;
            float4 lo = *(const float4*)(kr);
            float4 hi = *(const float4*)(kr + 4);
            int p = (j & 7) * 4;
            uint4 s1 = make_uint4(f2tf32(lo.x), f2tf32(hi.x), f2tf32(lo.y), f2tf32(hi.y));
            uint4 s2 = make_uint4(f2tf32(lo.z), f2tf32(hi.z), f2tf32(lo.w), f2tf32(hi.w));
            *(uint4*)&Ks[ds][j >> 3][p][0]     = s1;   // words 2p..2p+3
            *(uint4*)&Ks[ds][j >> 3][p + 2][0] = s2;   // words 2p+4..2p+7
        }
        // ---- load V tile (row-permuted fragment layout)
#pragma unroll
        for (int cc = 0; cc < 4; cc++) {
            int c = tid + cc * 128;
            int j = c & 63;                 // key
            int dstep = c >> 6;             // dk chunk of 8
            const float* vr = qkv + (size_t)(b * T_SZ + kt + j) * D3 + 2 * D_SZ + h * DK_SZ + dstep * 8;
            float4 lo = *(const float4*)(vr);
            float4 hi = *(const float4*)(vr + 4);
            int kap = ((j & 1) << 2) | ((j & 7) >> 1);  // psi^-1(j&7)
            int sl = kap >> 2, k3 = kap & 3;
            int jt = j >> 3;
            Vs[jt][dstep][0 * 4 + k3][sl] = f2tf32(lo.x);
            Vs[jt][dstep][1 * 4 + k3][sl] = f2tf32(lo.y);
            Vs[jt][dstep][2 * 4 + k3][sl] = f2tf32(lo.z);
            Vs[jt][dstep][3 * 4 + k3][sl] = f2tf32(lo.w);
            Vs[jt][dstep][4 * 4 + k3][sl] = f2tf32(hi.x);
            Vs[jt][dstep][5 * 4 + k3][sl] = f2tf32(hi.y);
            Vs[jt][dstep][6 * 4 + k3][sl] = f2tf32(hi.z);
            Vs[jt][dstep][7 * 4 + k3][sl] = f2tf32(hi.w);
        }
        __syncthreads();

        if (kt < kend_w) {
            // ---- S = Q @ K^T
            float sacc[8][4];
#pragma unroll
            for (int nt = 0; nt < 8; nt++)
#pragma unroll
                for (int e = 0; e < 4; e++) sacc[nt][e] = 0.0f;

#pragma unroll
            for (int nt = 0; nt < 8; nt++)
#pragma unroll
                for (int g = 0; g < 8; g++) {
                    uint2 bf = *(const uint2*)&Ks[g][nt][lane][0];
                    mma_tf32(sacc[nt], aq[g], bf);
                }

            // ---- mask (boundary tiles only)
            if (kt + AT_TK > min_end_w) {
#pragma unroll
                for (int nt = 0; nt < 8; nt++) {
                    int k0 = kt + nt * 8 + (lane & 3) * 2;
                    if (k0 >= enda)     sacc[nt][0] = -1e30f;
                    if (k0 + 1 >= enda) sacc[nt][1] = -1e30f;
                    if (k0 >= endb)     sacc[nt][2] = -1e30f;
                    if (k0 + 1 >= endb) sacc[nt][3] = -1e30f;
                }
            }

            // ---- row max (thread-local then quad reduce)
            float tm0 = -1e30f, tm1 = -1e30f;
#pragma unroll
            for (int nt = 0; nt < 8; nt++) {
                tm0 = fmaxf(tm0, fmaxf(sacc[nt][0], sacc[nt][1]));
                tm1 = fmaxf(tm1, fmaxf(sacc[nt][2], sacc[nt][3]));
            }
            tm0 = fmaxf(tm0, __shfl_xor_sync(0xffffffffu, tm0, 1));
            tm0 = fmaxf(tm0, __shfl_xor_sync(0xffffffffu, tm0, 2));
            tm1 = fmaxf(tm1, __shfl_xor_sync(0xffffffffu, tm1, 1));
            tm1 = fmaxf(tm1, __shfl_xor_sync(0xffffffffu, tm1, 2));

            float mn0 = fmaxf(m0, tm0);
            float mn1 = fmaxf(m1, tm1);
            float corr0 = __expf(m0 - mn0);
            float corr1 = __expf(m1 - mn1);
            m0 = mn0; m1 = mn1;

            // rescale O before accumulating this tile
#pragma unroll
            for (int dt = 0; dt < 8; dt++) {
                oacc[dt][0] *= corr0; oacc[dt][1] *= corr0;
                oacc[dt][2] *= corr1; oacc[dt][3] *= corr1;
            }

            // ---- exp + P@V (A-frag from C-frag remap {c0,c2,c1,c3})
            float ts0 = 0.0f, ts1 = 0.0f;
#pragma unroll
            for (int g = 0; g < 8; g++) {
                float p0 = __expf(sacc[g][0] - mn0);
                float p1 = __expf(sacc[g][1] - mn0);
                float p2 = __expf(sacc[g][2] - mn1);
                float p3 = __expf(sacc[g][3] - mn1);
                ts0 += p0 + p1;
                ts1 += p2 + p3;
                uint4 apg = make_uint4(f2tf32(p0), f2tf32(p2), f2tf32(p1), f2tf32(p3));
#pragma unroll
                for (int dt = 0; dt < 8; dt++) {
                    uint2 vf = *(const uint2*)&Vs[g][dt][lane][0];
                    mma_tf32(oacc[dt], apg, vf);
                }
            }
            ts0 += __shfl_xor_sync(0xffffffffu, ts0, 1);
            ts0 += __shfl_xor_sync(0xffffffffu, ts0, 2);
            ts1 += __shfl_xor_sync(0xffffffffu, ts1, 1);
            ts1 += __shfl_xor_sync(0xffffffffu, ts1, 2);
            l0 = l0 * corr0 + ts0;
            l1 = l1 * corr1 + ts1;
        }
        __syncthreads();
    }

    const float inv0 = 1.0f / l0;
    const float inv1 = 1.0f / l1;
    float* oA = out + (size_t)(b * T_SZ + qa) * D_SZ + h * DK_SZ + (lane & 3) * 2;
    float* oB = out + (size_t)(b * T_SZ + qb) * D_SZ + h * DK_SZ + (lane & 3) * 2;
#pragma unroll
    for (int dt = 0; dt < 8; dt++) {
        *(float2*)(oA + dt * 8) = make_float2(oacc[dt][0] * inv0, oacc[dt][1] * inv0);
        *(float2*)(oB + dt * 8) = make_float2(oacc[dt][2] * inv1, oacc[dt][3] * inv1);
    }
}

// ---------------------------------------------------------------------------
// launch
// ---------------------------------------------------------------------------
extern "C" void kernel_launch(void* const* d_in, const int* in_sizes, int n_in,
                              void* d_out, int out_size) {
    const float* x = (const float*)d_in[0];
    const int* prefix_raw = (const int*)d_in[1];
    const float* W_qkv = (const float*)d_in[2];
    const float* W_o = (const float*)d_in[3];
    float* out = (float*)d_out;

    float* qkv = nullptr;
    float* attn = nullptr;
    cudaGetSymbolAddress((void**)&qkv, g_qkv);
    cudaGetSymbolAddress((void**)&attn, g_attn);

    const int M = B_SZ * T_SZ;  // 8192

    decode_prefix_kernel<<<1, 1>>>(prefix_raw);

    // 1) qkv = x @ W_qkv^T   [8192, 3072]
    {
        dim3 grid(D3 / TBN, M / TBM);
        gemm_tf32_nt<<<grid, 256>>>(x, W_qkv, qkv, M, D3, D_SZ);
    }

    // 2) attention -> attn [8192, 1024]
    {
        dim3 grid(T_SZ / AT_TQ, H_SZ, B_SZ);
        attn_mma_kernel<<<grid, 128>>>(qkv, attn);
    }

    // 3) out = attn @ W_o^T  [8192, 1024]
    {
        dim3 grid(D_SZ / TBN, M / TBM);
        gemm_tf32_nt<<<grid, 256>>>(attn, W_o, out, M, D_SZ, D_SZ);
    }
}

// round 8
// speedup vs baseline: 5.2015x; 1.2310x over previous
#include <cuda_runtime.h>
#include <cuda_bf16.h>
#include <math.h>

// Problem constants
#define B_SZ 4
#define T_SZ 2048
#define D_SZ 1024
#define H_SZ 16
#define DK_SZ 64
#define D3 (3 * D_SZ)

// Scratch (device globals; no allocation allowed)
__device__ __align__(16) float g_qkv[(size_t)B_SZ * T_SZ * D3];    // 96 MB
__device__ __align__(16) float g_attn[(size_t)B_SZ * T_SZ * D_SZ]; // 32 MB
__device__ int g_prefix[B_SZ];

// ---------------------------------------------------------------------------
// Prefix decode (robust to int32 or int64 storage).
// ---------------------------------------------------------------------------
__global__ void decode_prefix_kernel(const int* __restrict__ raw) {
    bool is64 = (raw[1] == 0) && (raw[3] == 0);
    for (int b = 0; b < B_SZ; b++) {
        int p = is64 ? raw[2 * b] : raw[b];
        if (p < 0) p = 0;
        if (p > T_SZ) p = T_SZ;
        g_prefix[b] = p;
    }
}

// ---------------------------------------------------------------------------
// Common tf32 mma helpers
// ---------------------------------------------------------------------------
__device__ __forceinline__ unsigned f2tf32(float v) {
    unsigned u;
    asm("cvt.rna.tf32.f32 %0, %1;" : "=r"(u) : "f"(v));
    return u;
}

__device__ __forceinline__ void mma_tf32(float* c, const uint4& a, const uint2& b) {
    asm volatile(
        "mma.sync.aligned.m16n8k8.row.col.f32.tf32.tf32.f32 "
        "{%0,%1,%2,%3}, {%4,%5,%6,%7}, {%8,%9}, {%0,%1,%2,%3};"
        : "+f"(c[0]), "+f"(c[1]), "+f"(c[2]), "+f"(c[3])
        : "r"(a.x), "r"(a.y), "r"(a.z), "r"(a.w), "r"(b.x), "r"(b.y));
}

// ---------------------------------------------------------------------------
// TF32 tensor-core GEMM: C[M,N] = A[M,K] @ W[N,K]^T  (row-major, K contig)
// BM=128, BN=128, BK=16, 256 threads = 8 warps (2x4), warp tile 64x32.
// Fragment-direct smem fill: each thread gathers whole mma fragments with
// scalar LDG and stores them vectorized + conflict-free (word = lane*4/2).
// ---------------------------------------------------------------------------
#define TBM 128
#define TBN 128
#define TBK 16

__global__ __launch_bounds__(256)
void gemm_tf32_nt(const float* __restrict__ A, const float* __restrict__ W,
                  float* __restrict__ C, int M, int N, int K) {
    __shared__ unsigned As[2][2][8][32][4];   // [buf][ks][mt][lane][slot] 16KB
    __shared__ unsigned Bs[2][2][16][32][2];  // [buf][ks][nt][lane][slot] 16KB

    const int tid = threadIdx.x;
    const int warp = tid >> 5;
    const int lane = tid & 31;
    const int wm = warp >> 2;
    const int wn = warp & 3;

    const int row0 = blockIdx.y * TBM;
    const int col0 = blockIdx.x * TBN;

    // fragment-fill roles (uniform per warp)
    const int fks = (tid >> 5) & 1;   // ks this thread fills
    const int fmt = tid >> 6;         // A mtile (0..3); also fills fmt+4
    const int fnt = tid >> 6;         // B ntile base (0..3); fills +4,+8,+12

    const float* aptr = A + (size_t)(row0 + fmt * 16 + (lane >> 2)) * K + fks * 8 + (lane & 3);
    const float* bptr = W + (size_t)(col0 + fnt * 8 + (lane >> 2)) * K + fks * 8 + (lane & 3);
    const size_t a2off = (size_t)64 * K;   // mtile +4 = +64 rows
    const size_t r8 = (size_t)8 * K;       // +8 rows
    const size_t n32 = (size_t)32 * K;     // ntile +4 = +32 rows

    float acc[4][4][4];
#pragma unroll
    for (int i = 0; i < 4; i++)
#pragma unroll
        for (int j = 0; j < 4; j++)
#pragma unroll
            for (int c = 0; c < 4; c++) acc[i][j][c] = 0.0f;

    float fa[8], fb[8];
    // prologue fetch (tile 0)
    {
        fa[0] = aptr[0];        fa[1] = aptr[r8];        fa[2] = aptr[4];        fa[3] = aptr[r8 + 4];
        fa[4] = aptr[a2off];    fa[5] = aptr[a2off + r8]; fa[6] = aptr[a2off + 4]; fa[7] = aptr[a2off + r8 + 4];
#pragma unroll
        for (int i = 0; i < 4; i++) {
            fb[2 * i]     = bptr[(size_t)i * n32];
            fb[2 * i + 1] = bptr[(size_t)i * n32 + 4];
        }
    }
    int buf = 0;
    {
        *(uint4*)&As[buf][fks][fmt][lane][0] =
            make_uint4(f2tf32(fa[0]), f2tf32(fa[1]), f2tf32(fa[2]), f2tf32(fa[3]));
        *(uint4*)&As[buf][fks][fmt + 4][lane][0] =
            make_uint4(f2tf32(fa[4]), f2tf32(fa[5]), f2tf32(fa[6]), f2tf32(fa[7]));
#pragma unroll
        for (int i = 0; i < 4; i++)
            *(uint2*)&Bs[buf][fks][fnt + 4 * i][lane][0] =
                make_uint2(f2tf32(fb[2 * i]), f2tf32(fb[2 * i + 1]));
    }
    __syncthreads();

    const int nIter = K / TBK;
    for (int it = 0; it < nIter; it++) {
        const bool pre = (it + 1 < nIter);
        if (pre) {
            const int ko = (it + 1) * TBK;
            fa[0] = aptr[ko];            fa[1] = aptr[ko + r8];
            fa[2] = aptr[ko + 4];        fa[3] = aptr[ko + r8 + 4];
            fa[4] = aptr[ko + a2off];    fa[5] = aptr[ko + a2off + r8];
            fa[6] = aptr[ko + a2off + 4];fa[7] = aptr[ko + a2off + r8 + 4];
#pragma unroll
            for (int i = 0; i < 4; i++) {
                fb[2 * i]     = bptr[ko + (size_t)i * n32];
                fb[2 * i + 1] = bptr[ko + (size_t)i * n32 + 4];
            }
        }

#pragma unroll
        for (int ks = 0; ks < 2; ks++) {
            uint4 af[4];
            uint2 bf[4];
#pragma unroll
            for (int mt = 0; mt < 4; mt++)
                af[mt] = *reinterpret_cast<const uint4*>(&As[buf][ks][wm * 4 + mt][lane][0]);
#pragma unroll
            for (int nt = 0; nt < 4; nt++)
                bf[nt] = *reinterpret_cast<const uint2*>(&Bs[buf][ks][wn * 4 + nt][lane][0]);
#pragma unroll
            for (int mt = 0; mt < 4; mt++)
#pragma unroll
                for (int nt = 0; nt < 4; nt++)
                    mma_tf32(acc[mt][nt], af[mt], bf[nt]);
        }

        if (pre) {
            int nb = buf ^ 1;
            *(uint4*)&As[nb][fks][fmt][lane][0] =
                make_uint4(f2tf32(fa[0]), f2tf32(fa[1]), f2tf32(fa[2]), f2tf32(fa[3]));
            *(uint4*)&As[nb][fks][fmt + 4][lane][0] =
                make_uint4(f2tf32(fa[4]), f2tf32(fa[5]), f2tf32(fa[6]), f2tf32(fa[7]));
#pragma unroll
            for (int i = 0; i < 4; i++)
                *(uint2*)&Bs[nb][fks][fnt + 4 * i][lane][0] =
                    make_uint2(f2tf32(fb[2 * i]), f2tf32(fb[2 * i + 1]));
            __syncthreads();
            buf = nb;
        }
    }

    const int r_base = row0 + wm * 64 + (lane >> 2);
    const int c_base = col0 + wn * 32 + (lane & 3) * 2;
#pragma unroll
    for (int mt = 0; mt < 4; mt++) {
#pragma unroll
        for (int nt = 0; nt < 4; nt++) {
            int r = r_base + mt * 16;
            int c = c_base + nt * 8;
            *(float2*)&C[(size_t)r * N + c] =
                make_float2(acc[mt][nt][0], acc[mt][nt][1]);
            *(float2*)&C[(size_t)(r + 8) * N + c] =
                make_float2(acc[mt][nt][2], acc[mt][nt][3]);
        }
    }
}

// ---------------------------------------------------------------------------
// Tensor-core flash attention (prefix-LM mask).
// Block: 256 threads = 8 warps; 128 queries per block (16/warp), one (b,h).
// K tiles of 64 keys. S = Q@K^T and O += P@V via m16n8k8 tf32 mma.
// Softmax in exp2 domain (log2e folded into Q scale).
//
// P@V: A-frag of P from S C-frag register remap {c0,c2,c1,c3}; then mma
// k-slot kk <-> physical key psi(kk) with psi(k3)=2*k3, psi(k3+4)=2*k3+1,
// so the B-frag uint2 is two CONSECUTIVE keys. V stored key-contiguous:
//   Vs[g][dt][i ^ g][key8]   (i = dk slot within octet; XOR kills the
//   4-way g-group store conflicts; loads stay conflict-free LDS.64)
// ---------------------------------------------------------------------------
#define AT_TQ 128
#define AT_TK 64

__global__ __launch_bounds__(256)
void attn_mma_kernel(const float* __restrict__ qkv, float* __restrict__ out) {
    __shared__ unsigned Ks[8][8][32][2];  // [dk-octet][key-octet][lane][slot] 16KB
    __shared__ unsigned Vs[8][8][8][8];   // [key-octet g][dk-octet dt][dk^g][key] 16KB

    const int b = blockIdx.z;
    const int h = blockIdx.y;
    const int q0 = blockIdx.x * AT_TQ;
    const int tid = threadIdx.x;
    const int warp = tid >> 5;
    const int lane = tid & 31;

    const int P = g_prefix[b];

    const int q0w = q0 + warp * 16;
    const int qa = q0w + (lane >> 2);
    const int qb = qa + 8;
    const int enda = (qa < P) ? P : (qa + 1);
    const int endb = (qb < P) ? P : (qb + 1);
    const int min_end_w = (q0w < P) ? P : (q0w + 1);

    int kend_w = q0w + 16;
    if (P > kend_w) kend_w = P;
    if (kend_w > T_SZ) kend_w = T_SZ;
    int kend = q0 + AT_TQ;
    if (P > kend) kend = P;
    if (kend > T_SZ) kend = T_SZ;

    // Q fragments; scale = log2(e)/sqrt(64) so softmax runs in exp2 domain
    const float qscale = 0.125f * 1.4426950408889634f;
    uint4 aq[8];
    {
        const float* qrA = qkv + (size_t)(b * T_SZ + qa) * D3 + h * DK_SZ;
        const float* qrB = qkv + (size_t)(b * T_SZ + qb) * D3 + h * DK_SZ;
        const int c = lane & 3;
#pragma unroll
        for (int g = 0; g < 8; g++) {
            aq[g].x = f2tf32(qrA[g * 8 + c] * qscale);
            aq[g].y = f2tf32(qrB[g * 8 + c] * qscale);
            aq[g].z = f2tf32(qrA[g * 8 + c + 4] * qscale);
            aq[g].w = f2tf32(qrB[g * 8 + c + 4] * qscale);
        }
    }

    float oacc[8][4];
#pragma unroll
    for (int dt = 0; dt < 8; dt++)
#pragma unroll
        for (int e = 0; e < 4; e++) oacc[dt][e] = 0.0f;
    float m0 = -1e30f, m1 = -1e30f, l0 = 0.0f, l1 = 0.0f;

    for (int kt = 0; kt < kend; kt += AT_TK) {
        // ---- K tile -> fragment layout (512 tasks; 2 per thread)
#pragma unroll
        for (int cc = 0; cc < 2; cc++) {
            int c = tid + cc * 256;         // 0..511
            int j = c & 63;                 // key within tile
            int ds = c >> 6;                // dk octet
            const float* kr = qkv + (size_t)(b * T_SZ + kt + j) * D3 + D_SZ + h * DK_SZ + ds * 8;
            float4 lo = *(const float4*)(kr);
            float4 hi = *(const float4*)(kr + 4);
            int p = (j & 7) * 4;
            *(uint4*)&Ks[ds][j >> 3][p][0] =
                make_uint4(f2tf32(lo.x), f2tf32(hi.x), f2tf32(lo.y), f2tf32(hi.y));
            *(uint4*)&Ks[ds][j >> 3][p + 2][0] =
                make_uint4(f2tf32(lo.z), f2tf32(hi.z), f2tf32(lo.w), f2tf32(hi.w));
        }
        // ---- V tile -> key-contiguous swizzled layout (512 tasks)
#pragma unroll
        for (int cc = 0; cc < 2; cc++) {
            int c = tid + cc * 256;
            int j = c & 63;                 // key
            int dstep = c >> 6;             // dk octet
            const float* vr = qkv + (size_t)(b * T_SZ + kt + j) * D3 + 2 * D_SZ + h * DK_SZ + dstep * 8;
            float4 lo = *(const float4*)(vr);
            float4 hi = *(const float4*)(vr + 4);
            int g = j >> 3, jk = j & 7;
            Vs[g][dstep][0 ^ g][jk] = f2tf32(lo.x);
            Vs[g][dstep][1 ^ g][jk] = f2tf32(lo.y);
            Vs[g][dstep][2 ^ g][jk] = f2tf32(lo.z);
            Vs[g][dstep][3 ^ g][jk] = f2tf32(lo.w);
            Vs[g][dstep][4 ^ g][jk] = f2tf32(hi.x);
            Vs[g][dstep][5 ^ g][jk] = f2tf32(hi.y);
            Vs[g][dstep][6 ^ g][jk] = f2tf32(hi.z);
            Vs[g][dstep][7 ^ g][jk] = f2tf32(hi.w);
        }
        __syncthreads();

        if (kt < kend_w) {
            // ---- S = Q @ K^T
            float sacc[8][4];
#pragma unroll
            for (int nt = 0; nt < 8; nt++)
#pragma unroll
                for (int e = 0; e < 4; e++) sacc[nt][e] = 0.0f;

#pragma unroll
            for (int nt = 0; nt < 8; nt++)
#pragma unroll
                for (int g = 0; g < 8; g++) {
                    uint2 bf = *(const uint2*)&Ks[g][nt][lane][0];
                    mma_tf32(sacc[nt], aq[g], bf);
                }

            // ---- mask (boundary tiles only)
            if (kt + AT_TK > min_end_w) {
#pragma unroll
                for (int nt = 0; nt < 8; nt++) {
                    int k0 = kt + nt * 8 + (lane & 3) * 2;
                    if (k0 >= enda)     sacc[nt][0] = -1e30f;
                    if (k0 + 1 >= enda) sacc[nt][1] = -1e30f;
                    if (k0 >= endb)     sacc[nt][2] = -1e30f;
                    if (k0 + 1 >= endb) sacc[nt][3] = -1e30f;
                }
            }

            // ---- row max (thread-local then quad reduce)
            float tm0 = -1e30f, tm1 = -1e30f;
#pragma unroll
            for (int nt = 0; nt < 8; nt++) {
                tm0 = fmaxf(tm0, fmaxf(sacc[nt][0], sacc[nt][1]));
                tm1 = fmaxf(tm1, fmaxf(sacc[nt][2], sacc[nt][3]));
            }
            tm0 = fmaxf(tm0, __shfl_xor_sync(0xffffffffu, tm0, 1));
            tm0 = fmaxf(tm0, __shfl_xor_sync(0xffffffffu, tm0, 2));
            tm1 = fmaxf(tm1, __shfl_xor_sync(0xffffffffu, tm1, 1));
            tm1 = fmaxf(tm1, __shfl_xor_sync(0xffffffffu, tm1, 2));

            float mn0 = fmaxf(m0, tm0);
            float mn1 = fmaxf(m1, tm1);
            float corr0 = exp2f(m0 - mn0);
            float corr1 = exp2f(m1 - mn1);
            m0 = mn0; m1 = mn1;

#pragma unroll
            for (int dt = 0; dt < 8; dt++) {
                oacc[dt][0] *= corr0; oacc[dt][1] *= corr0;
                oacc[dt][2] *= corr1; oacc[dt][3] *= corr1;
            }

            // ---- exp2 + P@V
            float ts0 = 0.0f, ts1 = 0.0f;
#pragma unroll
            for (int g = 0; g < 8; g++) {
                float p0 = exp2f(sacc[g][0] - mn0);
                float p1 = exp2f(sacc[g][1] - mn0);
                float p2 = exp2f(sacc[g][2] - mn1);
                float p3 = exp2f(sacc[g][3] - mn1);
                ts0 += p0 + p1;
                ts1 += p2 + p3;
                uint4 apg = make_uint4(f2tf32(p0), f2tf32(p2), f2tf32(p1), f2tf32(p3));
#pragma unroll
                for (int dt = 0; dt < 8; dt++) {
                    uint2 vf = *(const uint2*)&Vs[g][dt][(lane >> 2) ^ g][2 * (lane & 3)];
                    mma_tf32(oacc[dt], apg, vf);
                }
            }
            ts0 += __shfl_xor_sync(0xffffffffu, ts0, 1);
            ts0 += __shfl_xor_sync(0xffffffffu, ts0, 2);
            ts1 += __shfl_xor_sync(0xffffffffu, ts1, 1);
            ts1 += __shfl_xor_sync(0xffffffffu, ts1, 2);
            l0 = l0 * corr0 + ts0;
            l1 = l1 * corr1 + ts1;
        }
        __syncthreads();
    }

    const float inv0 = 1.0f / l0;
    const float inv1 = 1.0f / l1;
    float* oA = out + (size_t)(b * T_SZ + qa) * D_SZ + h * DK_SZ + (lane & 3) * 2;
    float* oB = out + (size_t)(b * T_SZ + qb) * D_SZ + h * DK_SZ + (lane & 3) * 2;
#pragma unroll
    for (int dt = 0; dt < 8; dt++) {
        *(float2*)(oA + dt * 8) = make_float2(oacc[dt][0] * inv0, oacc[dt][1] * inv0);
        *(float2*)(oB + dt * 8) = make_float2(oacc[dt][2] * inv1, oacc[dt][3] * inv1);
    }
}

// ---------------------------------------------------------------------------
// launch
// ---------------------------------------------------------------------------
extern "C" void kernel_launch(void* const* d_in, const int* in_sizes, int n_in,
                              void* d_out, int out_size) {
    const float* x = (const float*)d_in[0];
    const int* prefix_raw = (const int*)d_in[1];
    const float* W_qkv = (const float*)d_in[2];
    const float* W_o = (const float*)d_in[3];
    float* out = (float*)d_out;

    float* qkv = nullptr;
    float* attn = nullptr;
    cudaGetSymbolAddress((void**)&qkv, g_qkv);
    cudaGetSymbolAddress((void**)&attn, g_attn);

    const int M = B_SZ * T_SZ;  // 8192

    decode_prefix_kernel<<<1, 1>>>(prefix_raw);

    // 1) qkv = x @ W_qkv^T   [8192, 3072]
    {
        dim3 grid(D3 / TBN, M / TBM);
        gemm_tf32_nt<<<grid, 256>>>(x, W_qkv, qkv, M, D3, D_SZ);
    }

    // 2) attention -> attn [8192, 1024]
    {
        dim3 grid(T_SZ / AT_TQ, H_SZ, B_SZ);
        attn_mma_kernel<<<grid, 256>>>(qkv, attn);
    }

    // 3) out = attn @ W_o^T  [8192, 1024]
    {
        dim3 grid(D_SZ / TBN, M / TBM);
        gemm_tf32_nt<<<grid, 256>>>(attn, W_o, out, M, D_SZ, D_SZ);
    }
}

// round 11
// speedup vs baseline: 5.6329x; 1.0829x over previous
#include <cuda_runtime.h>
#include <cuda_bf16.h>
#include <math.h>

// Problem constants
#define B_SZ 4
#define T_SZ 2048
#define D_SZ 1024
#define H_SZ 16
#define DK_SZ 64
#define D3 (3 * D_SZ)

// Scratch (device globals; no allocation allowed)
__device__ __align__(16) float g_qkv[(size_t)B_SZ * T_SZ * D3];    // 96 MB
__device__ __align__(16) float g_attn[(size_t)B_SZ * T_SZ * D_SZ]; // 32 MB
__device__ int g_prefix[B_SZ];

// ---------------------------------------------------------------------------
// Prefix decode (robust to int32 or int64 storage).
// ---------------------------------------------------------------------------
__global__ void decode_prefix_kernel(const int* __restrict__ raw) {
    bool is64 = (raw[1] == 0) && (raw[3] == 0);
    for (int b = 0; b < B_SZ; b++) {
        int p = is64 ? raw[2 * b] : raw[b];
        if (p < 0) p = 0;
        if (p > T_SZ) p = T_SZ;
        g_prefix[b] = p;
    }
}

// ---------------------------------------------------------------------------
// Common tf32 mma helpers
// ---------------------------------------------------------------------------
__device__ __forceinline__ unsigned f2tf32(float v) {
    unsigned u;
    asm("cvt.rna.tf32.f32 %0, %1;" : "=r"(u) : "f"(v));
    return u;
}

__device__ __forceinline__ void mma_tf32(float* c, const uint4& a, const uint2& b) {
    asm volatile(
        "mma.sync.aligned.m16n8k8.row.col.f32.tf32.tf32.f32 "
        "{%0,%1,%2,%3}, {%4,%5,%6,%7}, {%8,%9}, {%0,%1,%2,%3};"
        : "+f"(c[0]), "+f"(c[1]), "+f"(c[2]), "+f"(c[3])
        : "r"(a.x), "r"(a.y), "r"(a.z), "r"(a.w), "r"(b.x), "r"(b.y));
}

// ---------------------------------------------------------------------------
// TF32 tensor-core GEMM: C[M,N] = A[M,K] @ W[N,K]^T  (row-major, K contig)
// BM=128, BN=128, BK=16. 128 threads = 4 warps (2x2), warp tile 64x64.
// Fragment-direct smem fill (conflict-free vector STS at word = lane*4/2).
// ---------------------------------------------------------------------------
#define TBM 128
#define TBN 128
#define TBK 16

__global__ __launch_bounds__(128)
void gemm_tf32_nt(const float* __restrict__ A, const float* __restrict__ W,
                  float* __restrict__ C, int M, int N, int K) {
    __shared__ unsigned As[2][2][8][32][4];   // [buf][ks][mt][lane][slot] 16KB
    __shared__ unsigned Bs[2][2][16][32][2];  // [buf][ks][nt][lane][slot] 16KB

    const int tid = threadIdx.x;
    const int warp = tid >> 5;
    const int lane = tid & 31;
    const int wm = warp >> 1;   // 0..1 -> m offset wm*64
    const int wn = warp & 1;    // 0..1 -> n offset wn*64

    const int row0 = blockIdx.y * TBM;
    const int col0 = blockIdx.x * TBN;

    const int fks = (tid >> 5) & 1;
    const int fb = tid >> 6;          // 0..1

    const float* aptr = A + (size_t)(row0 + fb * 16 + (lane >> 2)) * K + fks * 8 + (lane & 3);
    const float* bptr = W + (size_t)(col0 + fb * 8 + (lane >> 2)) * K + fks * 8 + (lane & 3);
    const size_t r8 = (size_t)8 * K;
    const size_t m32 = (size_t)32 * K;   // A mtile +2
    const size_t n16 = (size_t)16 * K;   // B ntile +2

    float acc[4][8][4];
#pragma unroll
    for (int i = 0; i < 4; i++)
#pragma unroll
        for (int j = 0; j < 8; j++)
#pragma unroll
            for (int c = 0; c < 4; c++) acc[i][j][c] = 0.0f;

    float fa[16], fbv[16];
#pragma unroll
    for (int i = 0; i < 4; i++) {
        size_t o = (size_t)i * m32;
        fa[4 * i + 0] = aptr[o];
        fa[4 * i + 1] = aptr[o + r8];
        fa[4 * i + 2] = aptr[o + 4];
        fa[4 * i + 3] = aptr[o + r8 + 4];
    }
#pragma unroll
    for (int i = 0; i < 8; i++) {
        size_t o = (size_t)i * n16;
        fbv[2 * i]     = bptr[o];
        fbv[2 * i + 1] = bptr[o + 4];
    }

    int buf = 0;
    {
#pragma unroll
        for (int i = 0; i < 4; i++)
            *(uint4*)&As[buf][fks][fb + 2 * i][lane][0] =
                make_uint4(f2tf32(fa[4 * i]), f2tf32(fa[4 * i + 1]),
                           f2tf32(fa[4 * i + 2]), f2tf32(fa[4 * i + 3]));
#pragma unroll
        for (int i = 0; i < 8; i++)
            *(uint2*)&Bs[buf][fks][fb + 2 * i][lane][0] =
                make_uint2(f2tf32(fbv[2 * i]), f2tf32(fbv[2 * i + 1]));
    }
    __syncthreads();

    const int nIter = K / TBK;
    for (int it = 0; it < nIter; it++) {
        const bool pre = (it + 1 < nIter);
        if (pre) {
            const int ko = (it + 1) * TBK;
#pragma unroll
            for (int i = 0; i < 4; i++) {
                size_t o = ko + (size_t)i * m32;
                fa[4 * i + 0] = aptr[o];
                fa[4 * i + 1] = aptr[o + r8];
                fa[4 * i + 2] = aptr[o + 4];
                fa[4 * i + 3] = aptr[o + r8 + 4];
            }
#pragma unroll
            for (int i = 0; i < 8; i++) {
                size_t o = ko + (size_t)i * n16;
                fbv[2 * i]     = bptr[o];
                fbv[2 * i + 1] = bptr[o + 4];
            }
        }

#pragma unroll
        for (int ks = 0; ks < 2; ks++) {
            uint4 af[4];
            uint2 bf[8];
#pragma unroll
            for (int mt = 0; mt < 4; mt++)
                af[mt] = *reinterpret_cast<const uint4*>(&As[buf][ks][wm * 4 + mt][lane][0]);
#pragma unroll
            for (int nt = 0; nt < 8; nt++)
                bf[nt] = *reinterpret_cast<const uint2*>(&Bs[buf][ks][wn * 8 + nt][lane][0]);
#pragma unroll
            for (int mt = 0; mt < 4; mt++)
#pragma unroll
                for (int nt = 0; nt < 8; nt++)
                    mma_tf32(acc[mt][nt], af[mt], bf[nt]);
        }

        if (pre) {
            int nb = buf ^ 1;
#pragma unroll
            for (int i = 0; i < 4; i++)
                *(uint4*)&As[nb][fks][fb + 2 * i][lane][0] =
                    make_uint4(f2tf32(fa[4 * i]), f2tf32(fa[4 * i + 1]),
                               f2tf32(fa[4 * i + 2]), f2tf32(fa[4 * i + 3]));
#pragma unroll
            for (int i = 0; i < 8; i++)
                *(uint2*)&Bs[nb][fks][fb + 2 * i][lane][0] =
                    make_uint2(f2tf32(fbv[2 * i]), f2tf32(fbv[2 * i + 1]));
            __syncthreads();
            buf = nb;
        }
    }

    const int r_base = row0 + wm * 64 + (lane >> 2);
    const int c_base = col0 + wn * 64 + (lane & 3) * 2;
#pragma unroll
    for (int mt = 0; mt < 4; mt++) {
#pragma unroll
        for (int nt = 0; nt < 8; nt++) {
            int r = r_base + mt * 16;
            int c = c_base + nt * 8;
            *(float2*)&C[(size_t)r * N + c] =
                make_float2(acc[mt][nt][0], acc[mt][nt][1]);
            *(float2*)&C[(size_t)(r + 8) * N + c] =
                make_float2(acc[mt][nt][2], acc[mt][nt][3]);
        }
    }
}

// ---------------------------------------------------------------------------
// Tensor-core flash attention (prefix-LM mask).
// Block: 256 threads = 8 warps; 256 queries per block (32/warp), one (b,h).
// Each K/V fragment LDS feeds TWO mmas (two 16-row query frags).
// K tiles of 64 keys; softmax in exp2 domain.
// ---------------------------------------------------------------------------
#define AT_TQ 256
#define AT_TK 64

__global__ __launch_bounds__(256, 1)
void attn_mma_kernel(const float* __restrict__ qkv, float* __restrict__ out) {
    __shared__ unsigned Ks[8][8][32][2];  // [dk-octet][key-octet][lane][slot] 16KB
    __shared__ unsigned Vs[8][8][8][8];   // [key-octet g][dk-octet dt][dk^g][key] 16KB

    const int b = blockIdx.z;
    const int h = blockIdx.y;
    const int q0 = blockIdx.x * AT_TQ;
    const int tid = threadIdx.x;
    const int warp = tid >> 5;
    const int lane = tid & 31;

    const int P = g_prefix[b];

    const int q0w = q0 + warp * 32;
    const int qa = q0w + (lane >> 2);          // mf0 rows qa, qa+8
    const int qc = qa + 16;                    // mf1 rows qc, qc+8
    const int e0 = (qa < P) ? P : (qa + 1);
    const int e1 = (qa + 8 < P) ? P : (qa + 9);
    const int e2 = (qc < P) ? P : (qc + 1);
    const int e3 = (qc + 8 < P) ? P : (qc + 9);
    const int min_end_w = (q0w < P) ? P : (q0w + 1);

    int kend_w = q0w + 32;
    if (P > kend_w) kend_w = P;
    if (kend_w > T_SZ) kend_w = T_SZ;
    int kend = q0 + AT_TQ;
    if (P > kend) kend = P;
    if (kend > T_SZ) kend = T_SZ;

    // Q fragments for both 16-row groups; scale = log2(e)/8 (exp2 domain)
    const float qscale = 0.125f * 1.4426950408889634f;
    uint4 aq[8][2];
    {
        const int c = lane & 3;
        const float* q0p = qkv + (size_t)(b * T_SZ + qa) * D3 + h * DK_SZ;
        const float* q1p = q0p + (size_t)8 * D3;
        const float* q2p = q0p + (size_t)16 * D3;
        const float* q3p = q0p + (size_t)24 * D3;
#pragma unroll
        for (int g = 0; g < 8; g++) {
            aq[g][0].x = f2tf32(q0p[g * 8 + c] * qscale);
            aq[g][0].y = f2tf32(q1p[g * 8 + c] * qscale);
            aq[g][0].z = f2tf32(q0p[g * 8 + c + 4] * qscale);
            aq[g][0].w = f2tf32(q1p[g * 8 + c + 4] * qscale);
            aq[g][1].x = f2tf32(q2p[g * 8 + c] * qscale);
            aq[g][1].y = f2tf32(q3p[g * 8 + c] * qscale);
            aq[g][1].z = f2tf32(q2p[g * 8 + c + 4] * qscale);
            aq[g][1].w = f2tf32(q3p[g * 8 + c + 4] * qscale);
        }
    }

    float oacc[2][8][4];
#pragma unroll
    for (int mf = 0; mf < 2; mf++)
#pragma unroll
        for (int dt = 0; dt < 8; dt++)
#pragma unroll
            for (int e = 0; e < 4; e++) oacc[mf][dt][e] = 0.0f;
    float m0 = -1e30f, m1 = -1e30f, m2 = -1e30f, m3 = -1e30f;
    float l0 = 0.0f, l1 = 0.0f, l2 = 0.0f, l3 = 0.0f;

    for (int kt = 0; kt < kend; kt += AT_TK) {
        // ---- K tile -> fragment layout (512 tasks; 2 per thread)
#pragma unroll
        for (int cc = 0; cc < 2; cc++) {
            int c = tid + cc * 256;
            int j = c & 63;
            int ds = c >> 6;
            const float* kr = qkv + (size_t)(b * T_SZ + kt + j) * D3 + D_SZ + h * DK_SZ + ds * 8;
            float4 lo = *(const float4*)(kr);
            float4 hi = *(const float4*)(kr + 4);
            int p = (j & 7) * 4;
            *(uint4*)&Ks[ds][j >> 3][p][0] =
                make_uint4(f2tf32(lo.x), f2tf32(hi.x), f2tf32(lo.y), f2tf32(hi.y));
            *(uint4*)&Ks[ds][j >> 3][p + 2][0] =
                make_uint4(f2tf32(lo.z), f2tf32(hi.z), f2tf32(lo.w), f2tf32(hi.w));
        }
        // ---- V tile -> key-contiguous swizzled layout
#pragma unroll
        for (int cc = 0; cc < 2; cc++) {
            int c = tid + cc * 256;
            int j = c & 63;
            int dstep = c >> 6;
            const float* vr = qkv + (size_t)(b * T_SZ + kt + j) * D3 + 2 * D_SZ + h * DK_SZ + dstep * 8;
            float4 lo = *(const float4*)(vr);
            float4 hi = *(const float4*)(vr + 4);
            int g = j >> 3, jk = j & 7;
            Vs[g][dstep][0 ^ g][jk] = f2tf32(lo.x);
            Vs[g][dstep][1 ^ g][jk] = f2tf32(lo.y);
            Vs[g][dstep][2 ^ g][jk] = f2tf32(lo.z);
            Vs[g][dstep][3 ^ g][jk] = f2tf32(lo.w);
            Vs[g][dstep][4 ^ g][jk] = f2tf32(hi.x);
            Vs[g][dstep][5 ^ g][jk] = f2tf32(hi.y);
            Vs[g][dstep][6 ^ g][jk] = f2tf32(hi.z);
            Vs[g][dstep][7 ^ g][jk] = f2tf32(hi.w);
        }
        __syncthreads();

        if (kt < kend_w) {
            // ---- S = Q @ K^T (skip fully-masked key-octets; warp-uniform)
            float sacc[2][8][4];
#pragma unroll
            for (int mf = 0; mf < 2; mf++)
#pragma unroll
                for (int nt = 0; nt < 8; nt++)
#pragma unroll
                    for (int e = 0; e < 4; e++) sacc[mf][nt][e] = 0.0f;

#pragma unroll
            for (int nt = 0; nt < 8; nt++) {
                if (kt + nt * 8 < kend_w) {
#pragma unroll
                    for (int g = 0; g < 8; g++) {
                        uint2 bf = *(const uint2*)&Ks[g][nt][lane][0];
                        mma_tf32(sacc[0][nt], aq[g][0], bf);
                        mma_tf32(sacc[1][nt], aq[g][1], bf);
                    }
                }
            }

            // ---- mask (boundary tiles only)
            if (kt + AT_TK > min_end_w) {
#pragma unroll
                for (int nt = 0; nt < 8; nt++) {
                    int k0 = kt + nt * 8 + (lane & 3) * 2;
                    if (k0 >= e0)     sacc[0][nt][0] = -1e30f;
                    if (k0 + 1 >= e0) sacc[0][nt][1] = -1e30f;
                    if (k0 >= e1)     sacc[0][nt][2] = -1e30f;
                    if (k0 + 1 >= e1) sacc[0][nt][3] = -1e30f;
                    if (k0 >= e2)     sacc[1][nt][0] = -1e30f;
                    if (k0 + 1 >= e2) sacc[1][nt][1] = -1e30f;
                    if (k0 >= e3)     sacc[1][nt][2] = -1e30f;
                    if (k0 + 1 >= e3) sacc[1][nt][3] = -1e30f;
                }
            }

            // ---- row maxes
            float tm0 = -1e30f, tm1 = -1e30f, tm2 = -1e30f, tm3 = -1e30f;
#pragma unroll
            for (int nt = 0; nt < 8; nt++) {
                tm0 = fmaxf(tm0, fmaxf(sacc[0][nt][0], sacc[0][nt][1]));
                tm1 = fmaxf(tm1, fmaxf(sacc[0][nt][2], sacc[0][nt][3]));
                tm2 = fmaxf(tm2, fmaxf(sacc[1][nt][0], sacc[1][nt][1]));
                tm3 = fmaxf(tm3, fmaxf(sacc[1][nt][2], sacc[1][nt][3]));
            }
            tm0 = fmaxf(tm0, __shfl_xor_sync(0xffffffffu, tm0, 1));
            tm0 = fmaxf(tm0, __shfl_xor_sync(0xffffffffu, tm0, 2));
            tm1 = fmaxf(tm1, __shfl_xor_sync(0xffffffffu, tm1, 1));
            tm1 = fmaxf(tm1, __shfl_xor_sync(0xffffffffu, tm1, 2));
            tm2 = fmaxf(tm2, __shfl_xor_sync(0xffffffffu, tm2, 1));
            tm2 = fmaxf(tm2, __shfl_xor_sync(0xffffffffu, tm2, 2));
            tm3 = fmaxf(tm3, __shfl_xor_sync(0xffffffffu, tm3, 1));
            tm3 = fmaxf(tm3, __shfl_xor_sync(0xffffffffu, tm3, 2));

            float mn0 = fmaxf(m0, tm0), mn1 = fmaxf(m1, tm1);
            float mn2 = fmaxf(m2, tm2), mn3 = fmaxf(m3, tm3);
            float c0 = exp2f(m0 - mn0), c1 = exp2f(m1 - mn1);
            float c2 = exp2f(m2 - mn2), c3 = exp2f(m3 - mn3);
            m0 = mn0; m1 = mn1; m2 = mn2; m3 = mn3;

#pragma unroll
            for (int dt = 0; dt < 8; dt++) {
                oacc[0][dt][0] *= c0; oacc[0][dt][1] *= c0;
                oacc[0][dt][2] *= c1; oacc[0][dt][3] *= c1;
                oacc[1][dt][0] *= c2; oacc[1][dt][1] *= c2;
                oacc[1][dt][2] *= c3; oacc[1][dt][3] *= c3;
            }

            // ---- exp2 + P@V (skip fully-masked key-octets g)
            float ts0 = 0.0f, ts1 = 0.0f, ts2 = 0.0f, ts3 = 0.0f;
#pragma unroll
            for (int g = 0; g < 8; g++) {
                if (kt + g * 8 < kend_w) {
                    float p00 = exp2f(sacc[0][g][0] - mn0);
                    float p01 = exp2f(sacc[0][g][1] - mn0);
                    float p02 = exp2f(sacc[0][g][2] - mn1);
                    float p03 = exp2f(sacc[0][g][3] - mn1);
                    float p10 = exp2f(sacc[1][g][0] - mn2);
                    float p11 = exp2f(sacc[1][g][1] - mn2);
                    float p12 = exp2f(sacc[1][g][2] - mn3);
                    float p13 = exp2f(sacc[1][g][3] - mn3);
                    ts0 += p00 + p01; ts1 += p02 + p03;
                    ts2 += p10 + p11; ts3 += p12 + p13;
                    uint4 ap0 = make_uint4(f2tf32(p00), f2tf32(p02), f2tf32(p01), f2tf32(p03));
                    uint4 ap1 = make_uint4(f2tf32(p10), f2tf32(p12), f2tf32(p11), f2tf32(p13));
#pragma unroll
                    for (int dt = 0; dt < 8; dt++) {
                        uint2 vf = *(const uint2*)&Vs[g][dt][(lane >> 2) ^ g][2 * (lane & 3)];
                        mma_tf32(oacc[0][dt], ap0, vf);
                        mma_tf32(oacc[1][dt], ap1, vf);
                    }
                }
            }
            ts0 += __shfl_xor_sync(0xffffffffu, ts0, 1);
            ts0 += __shfl_xor_sync(0xffffffffu, ts0, 2);
            ts1 += __shfl_xor_sync(0xffffffffu, ts1, 1);
            ts1 += __shfl_xor_sync(0xffffffffu, ts1, 2);
            ts2 += __shfl_xor_sync(0xffffffffu, ts2, 1);
            ts2 += __shfl_xor_sync(0xffffffffu, ts2, 2);
            ts3 += __shfl_xor_sync(0xffffffffu, ts3, 1);
            ts3 += __shfl_xor_sync(0xffffffffu, ts3, 2);
            l0 = l0 * c0 + ts0;
            l1 = l1 * c1 + ts1;
            l2 = l2 * c2 + ts2;
            l3 = l3 * c3 + ts3;
        }
        __syncthreads();
    }

    const float i0 = 1.0f / l0, i1 = 1.0f / l1, i2 = 1.0f / l2, i3 = 1.0f / l3;
    float* o0 = out + (size_t)(b * T_SZ + qa) * D_SZ + h * DK_SZ + (lane & 3) * 2;
    float* o1 = o0 + (size_t)8 * D_SZ;
    float* o2 = o0 + (size_t)16 * D_SZ;
    float* o3 = o0 + (size_t)24 * D_SZ;
#pragma unroll
    for (int dt = 0; dt < 8; dt++) {
        *(float2*)(o0 + dt * 8) = make_float2(oacc[0][dt][0] * i0, oacc[0][dt][1] * i0);
        *(float2*)(o1 + dt * 8) = make_float2(oacc[0][dt][2] * i1, oacc[0][dt][3] * i1);
        *(float2*)(o2 + dt * 8) = make_float2(oacc[1][dt][0] * i2, oacc[1][dt][1] * i2);
        *(float2*)(o3 + dt * 8) = make_float2(oacc[1][dt][2] * i3, oacc[1][dt][3] * i3);
    }
}

// ---------------------------------------------------------------------------
// launch
// ---------------------------------------------------------------------------
extern "C" void kernel_launch(void* const* d_in, const int* in_sizes, int n_in,
                              void* d_out, int out_size) {
    const float* x = (const float*)d_in[0];
    const int* prefix_raw = (const int*)d_in[1];
    const float* W_qkv = (const float*)d_in[2];
    const float* W_o = (const float*)d_in[3];
    float* out = (float*)d_out;

    float* qkv = nullptr;
    float* attn = nullptr;
    cudaGetSymbolAddress((void**)&qkv, g_qkv);
    cudaGetSymbolAddress((void**)&attn, g_attn);

    const int M = B_SZ * T_SZ;  // 8192

    decode_prefix_kernel<<<1, 1>>>(prefix_raw);

    // 1) qkv = x @ W_qkv^T   [8192, 3072]
    {
        dim3 grid(D3 / TBN, M / TBM);
        gemm_tf32_nt<<<grid, 128>>>(x, W_qkv, qkv, M, D3, D_SZ);
    }

    // 2) attention -> attn [8192, 1024]
    {
        dim3 grid(T_SZ / AT_TQ, H_SZ, B_SZ);
        attn_mma_kernel<<<grid, 256>>>(qkv, attn);
    }

    // 3) out = attn @ W_o^T  [8192, 1024]
    {
        dim3 grid(D_SZ / TBN, M / TBM);
        gemm_tf32_nt<<<grid, 128>>>(attn, W_o, out, M, D_SZ, D_SZ);
    }
}

// round 14
// speedup vs baseline: 7.5978x; 1.3488x over previous
#include <cuda_runtime.h>
#include <cuda_bf16.h>
#include <math.h>
#include <stdint.h>

// Problem constants
#define B_SZ 4
#define T_SZ 2048
#define D_SZ 1024
#define H_SZ 16
#define DK_SZ 64
#define D3 (3 * D_SZ)

// Scratch (device globals; no allocation allowed)
__device__ __align__(16) float g_qkv[(size_t)B_SZ * T_SZ * D3];        // 96 MB, row-major fp32
__device__ __align__(16) unsigned g_attnfrag[(size_t)B_SZ * T_SZ * D_SZ]; // 32 MB, A-frag tf32
__device__ __align__(16) unsigned g_xfrag[(size_t)B_SZ * T_SZ * D_SZ];    // 32 MB, A-frag tf32
__device__ __align__(16) unsigned g_wqkvfrag[(size_t)D3 * D_SZ];          // 12 MB, B-frag tf32
__device__ __align__(16) unsigned g_wofrag[(size_t)D_SZ * D_SZ];          // 4 MB,  B-frag tf32
__device__ int g_prefix[B_SZ];

// ---------------------------------------------------------------------------
// Prefix decode (robust to int32 or int64 storage).
// ---------------------------------------------------------------------------
__global__ void decode_prefix_kernel(const int* __restrict__ raw) {
    bool is64 = (raw[1] == 0) && (raw[3] == 0);
    for (int b = 0; b < B_SZ; b++) {
        int p = is64 ? raw[2 * b] : raw[b];
        if (p < 0) p = 0;
        if (p > T_SZ) p = T_SZ;
        g_prefix[b] = p;
    }
}

// ---------------------------------------------------------------------------
// tf32 helpers
// ---------------------------------------------------------------------------
__device__ __forceinline__ unsigned f2tf32(float v) {
    unsigned u;
    asm("cvt.rna.tf32.f32 %0, %1;" : "=r"(u) : "f"(v));
    return u;
}

__device__ __forceinline__ void mma_tf32(float* c, const uint4& a, const uint2& b) {
    asm volatile(
        "mma.sync.aligned.m16n8k8.row.col.f32.tf32.tf32.f32 "
        "{%0,%1,%2,%3}, {%4,%5,%6,%7}, {%8,%9}, {%0,%1,%2,%3};"
        : "+f"(c[0]), "+f"(c[1]), "+f"(c[2]), "+f"(c[3])
        : "r"(a.x), "r"(a.y), "r"(a.z), "r"(a.w), "r"(b.x), "r"(b.y));
}

// ===========================================================================
// Fragment-layout gmem format (matches smem As/Bs blocks exactly).
// A (M x K): per 128-row block rb, per 16-k block it: 2048 words
//   word = (rb*K16+it)*2048 + ks*1024 + mt*128 + lane*4 + slot
//   element (r=m&127, k): ks=(k>>3)&1, mt=r>>4, lane=((r&7)<<2)|(k&3),
//                         slot=((r>>3)&1) + (((k>>2)&1)<<1)
// B (N x K): per 128-col block cb, per it: 2048 words
//   word = (cb*K16+it)*2048 + ks*1024 + nt*64 + lane*2 + slot
//   element (n=cn&127, k): nt=n>>3, lane=((n&7)<<2)|(k&3), slot=(k>>2)&1
// ===========================================================================

__global__ void prep_afrag(const float* __restrict__ A, uint4* __restrict__ dst,
                           int K, int nU4) {
    int U = blockIdx.x * 256 + threadIdx.x;
    if (U >= nU4) return;
    int K16 = K >> 4;
    int perRb = K16 * 512;
    int rb = U / perRb, rem = U % perRb;
    int it = rem >> 9, u = rem & 511;
    int ks = u >> 8, mt = (u >> 5) & 7, lane = u & 31;
    int r = rb * 128 + mt * 16 + (lane >> 2);
    int k = it * 16 + ks * 8 + (lane & 3);
    const float* p = A + (size_t)r * K + k;
    uint4 o;
    o.x = f2tf32(p[0]);
    o.y = f2tf32(p[(size_t)8 * K]);
    o.z = f2tf32(p[4]);
    o.w = f2tf32(p[(size_t)8 * K + 4]);
    dst[U] = o;
}

__global__ void prep_bfrag(const float* __restrict__ Bm, uint4* __restrict__ dst,
                           int K, int nU4) {
    int U = blockIdx.x * 256 + threadIdx.x;
    if (U >= nU4) return;
    int K16 = K >> 4;
    int perCb = K16 * 512;
    int cb = U / perCb, rem = U % perCb;
    int it = rem >> 9, u = rem & 511;
    int ks = u >> 8;
    int q = u & 255;                 // word-quad within ks half
    int nt = q >> 4;                 // 0..15
    int lane0 = (q << 1) & 31;       // even
    int n = cb * 128 + nt * 8 + (lane0 >> 2);
    int k = it * 16 + ks * 8 + (lane0 & 3);
    const float* p = Bm + (size_t)n * K + k;
    uint4 o;
    o.x = f2tf32(p[0]);   // lane0,   slot0 (k)
    o.y = f2tf32(p[4]);   // lane0,   slot1 (k+4)
    o.z = f2tf32(p[1]);   // lane0+1, slot0 (k+1)
    o.w = f2tf32(p[5]);   // lane0+1, slot1 (k+5)
    dst[U] = o;
}

// scatter one fp32 value into A-frag layout (K fixed = 1024 -> K16 = 64)
__device__ __forceinline__ void st_frag(unsigned* dst, int m, int k, float v) {
    size_t w = ((size_t)(m >> 7) * 64 + (k >> 4)) * 2048
             + (size_t)(((k >> 3) & 1) * 1024)
             + (size_t)(((m & 127) >> 4) * 128)
             + (size_t)(((((m & 7) << 2) | (k & 3))) * 4)
             + (size_t)(((m >> 3) & 1) + (((k >> 2) & 1) << 1));
    dst[w] = f2tf32(v);
}

// ===========================================================================
// GEMM from fragment-layout operands: C[M,N] = A @ B^T (fp32 out, row-major)
// Block 128x128, BK=16, 128 threads = 4 warps (2x2), warp tile 64x64.
// Fill: 8 coalesced LDG.128 + 8 conflict-free STS.128 per thread per iter.
// ===========================================================================
__global__ __launch_bounds__(128)
void gemm_frag_nt(const uint4* __restrict__ Af, const uint4* __restrict__ Bf,
                  float* __restrict__ C, int M, int N, int K) {
    __shared__ uint4 As[2][512];   // 8KB per buf
    __shared__ uint4 Bs[2][512];

    const int tid = threadIdx.x;
    const int warp = tid >> 5;
    const int lane = tid & 31;
    const int wm = warp >> 1;
    const int wn = warp & 1;
    const int K16 = K >> 4;

    const uint4* ab = Af + (size_t)blockIdx.y * K16 * 512;
    const uint4* bb = Bf + (size_t)blockIdx.x * K16 * 512;

    float acc[4][8][4];
#pragma unroll
    for (int i = 0; i < 4; i++)
#pragma unroll
        for (int j = 0; j < 8; j++)
#pragma unroll
            for (int c = 0; c < 4; c++) acc[i][j][c] = 0.0f;

    uint4 ra[4], rbv[4];
#pragma unroll
    for (int j = 0; j < 4; j++) {
        ra[j]  = ab[tid + j * 128];
        rbv[j] = bb[tid + j * 128];
    }
#pragma unroll
    for (int j = 0; j < 4; j++) {
        As[0][tid + j * 128] = ra[j];
        Bs[0][tid + j * 128] = rbv[j];
    }
    __syncthreads();

    int buf = 0;
    for (int it = 0; it < K16; it++) {
        const bool pre = (it + 1 < K16);
        if (pre) {
            const int base = (it + 1) * 512;
#pragma unroll
            for (int j = 0; j < 4; j++) {
                ra[j]  = ab[base + tid + j * 128];
                rbv[j] = bb[base + tid + j * 128];
            }
        }

        const unsigned* Au = (const unsigned*)As[buf];
        const unsigned* Bu = (const unsigned*)Bs[buf];
#pragma unroll
        for (int ks = 0; ks < 2; ks++) {
            uint4 af[4];
            uint2 bf[8];
#pragma unroll
            for (int mt = 0; mt < 4; mt++)
                af[mt] = *(const uint4*)&Au[(ks * 8 + wm * 4 + mt) * 128 + lane * 4];
#pragma unroll
            for (int nt = 0; nt < 8; nt++)
                bf[nt] = *(const uint2*)&Bu[(ks * 16 + wn * 8 + nt) * 64 + lane * 2];
#pragma unroll
            for (int mt = 0; mt < 4; mt++)
#pragma unroll
                for (int nt = 0; nt < 8; nt++)
                    mma_tf32(acc[mt][nt], af[mt], bf[nt]);
        }

        if (pre) {
            buf ^= 1;
#pragma unroll
            for (int j = 0; j < 4; j++) {
                As[buf][tid + j * 128] = ra[j];
                Bs[buf][tid + j * 128] = rbv[j];
            }
            __syncthreads();
        }
    }

    const int r_base = blockIdx.y * 128 + wm * 64 + (lane >> 2);
    const int c_base = blockIdx.x * 128 + wn * 64 + (lane & 3) * 2;
#pragma unroll
    for (int mt = 0; mt < 4; mt++) {
#pragma unroll
        for (int nt = 0; nt < 8; nt++) {
            int r = r_base + mt * 16;
            int c = c_base + nt * 8;
            *(float2*)&C[(size_t)r * N + c] =
                make_float2(acc[mt][nt][0], acc[mt][nt][1]);
            *(float2*)&C[(size_t)(r + 8) * N + c] =
                make_float2(acc[mt][nt][2], acc[mt][nt][3]);
        }
    }
}

// ---------------------------------------------------------------------------
// Tensor-core flash attention (prefix-LM mask). 256 queries/block, 32/warp.
// Epilogue writes O directly in A-frag layout (tf32) for GEMM3.
// ---------------------------------------------------------------------------
#define AT_TQ 256
#define AT_TK 64

__global__ __launch_bounds__(256, 1)
void attn_mma_kernel(const float* __restrict__ qkv, unsigned* __restrict__ outf) {
    __shared__ unsigned Ks[8][8][32][2];
    __shared__ unsigned Vs[8][8][8][8];

    const int b = blockIdx.z;
    const int h = blockIdx.y;
    const int q0 = blockIdx.x * AT_TQ;
    const int tid = threadIdx.x;
    const int warp = tid >> 5;
    const int lane = tid & 31;

    const int P = g_prefix[b];

    const int q0w = q0 + warp * 32;
    const int qa = q0w + (lane >> 2);
    const int qc = qa + 16;
    const int e0 = (qa < P) ? P : (qa + 1);
    const int e1 = (qa + 8 < P) ? P : (qa + 9);
    const int e2 = (qc < P) ? P : (qc + 1);
    const int e3 = (qc + 8 < P) ? P : (qc + 9);
    const int min_end_w = (q0w < P) ? P : (q0w + 1);

    int kend_w = q0w + 32;
    if (P > kend_w) kend_w = P;
    if (kend_w > T_SZ) kend_w = T_SZ;
    int kend = q0 + AT_TQ;
    if (P > kend) kend = P;
    if (kend > T_SZ) kend = T_SZ;

    const float qscale = 0.125f * 1.4426950408889634f;
    uint4 aq[8][2];
    {
        const int c = lane & 3;
        const float* q0p = qkv + (size_t)(b * T_SZ + qa) * D3 + h * DK_SZ;
        const float* q1p = q0p + (size_t)8 * D3;
        const float* q2p = q0p + (size_t)16 * D3;
        const float* q3p = q0p + (size_t)24 * D3;
#pragma unroll
        for (int g = 0; g < 8; g++) {
            aq[g][0].x = f2tf32(q0p[g * 8 + c] * qscale);
            aq[g][0].y = f2tf32(q1p[g * 8 + c] * qscale);
            aq[g][0].z = f2tf32(q0p[g * 8 + c + 4] * qscale);
            aq[g][0].w = f2tf32(q1p[g * 8 + c + 4] * qscale);
            aq[g][1].x = f2tf32(q2p[g * 8 + c] * qscale);
            aq[g][1].y = f2tf32(q3p[g * 8 + c] * qscale);
            aq[g][1].z = f2tf32(q2p[g * 8 + c + 4] * qscale);
            aq[g][1].w = f2tf32(q3p[g * 8 + c + 4] * qscale);
        }
    }

    float oacc[2][8][4];
#pragma unroll
    for (int mf = 0; mf < 2; mf++)
#pragma unroll
        for (int dt = 0; dt < 8; dt++)
#pragma unroll
            for (int e = 0; e < 4; e++) oacc[mf][dt][e] = 0.0f;
    float m0 = -1e30f, m1 = -1e30f, m2 = -1e30f, m3 = -1e30f;
    float l0 = 0.0f, l1 = 0.0f, l2 = 0.0f, l3 = 0.0f;

    for (int kt = 0; kt < kend; kt += AT_TK) {
#pragma unroll
        for (int cc = 0; cc < 2; cc++) {
            int c = tid + cc * 256;
            int j = c & 63;
            int ds = c >> 6;
            const float* kr = qkv + (size_t)(b * T_SZ + kt + j) * D3 + D_SZ + h * DK_SZ + ds * 8;
            float4 lo = *(const float4*)(kr);
            float4 hi = *(const float4*)(kr + 4);
            int p = (j & 7) * 4;
            *(uint4*)&Ks[ds][j >> 3][p][0] =
                make_uint4(f2tf32(lo.x), f2tf32(hi.x), f2tf32(lo.y), f2tf32(hi.y));
            *(uint4*)&Ks[ds][j >> 3][p + 2][0] =
                make_uint4(f2tf32(lo.z), f2tf32(hi.z), f2tf32(lo.w), f2tf32(hi.w));
        }
#pragma unroll
        for (int cc = 0; cc < 2; cc++) {
            int c = tid + cc * 256;
            int j = c & 63;
            int dstep = c >> 6;
            const float* vr = qkv + (size_t)(b * T_SZ + kt + j) * D3 + 2 * D_SZ + h * DK_SZ + dstep * 8;
            float4 lo = *(const float4*)(vr);
            float4 hi = *(const float4*)(vr + 4);
            int g = j >> 3, jk = j & 7;
            Vs[g][dstep][0 ^ g][jk] = f2tf32(lo.x);
            Vs[g][dstep][1 ^ g][jk] = f2tf32(lo.y);
            Vs[g][dstep][2 ^ g][jk] = f2tf32(lo.z);
            Vs[g][dstep][3 ^ g][jk] = f2tf32(lo.w);
            Vs[g][dstep][4 ^ g][jk] = f2tf32(hi.x);
            Vs[g][dstep][5 ^ g][jk] = f2tf32(hi.y);
            Vs[g][dstep][6 ^ g][jk] = f2tf32(hi.z);
            Vs[g][dstep][7 ^ g][jk] = f2tf32(hi.w);
        }
        __syncthreads();

        if (kt < kend_w) {
            float sacc[2][8][4];
#pragma unroll
            for (int mf = 0; mf < 2; mf++)
#pragma unroll
                for (int nt = 0; nt < 8; nt++)
#pragma unroll
                    for (int e = 0; e < 4; e++) sacc[mf][nt][e] = 0.0f;

#pragma unroll
            for (int nt = 0; nt < 8; nt++) {
                if (kt + nt * 8 < kend_w) {
#pragma unroll
                    for (int g = 0; g < 8; g++) {
                        uint2 bf = *(const uint2*)&Ks[g][nt][lane][0];
                        mma_tf32(sacc[0][nt], aq[g][0], bf);
                        mma_tf32(sacc[1][nt], aq[g][1], bf);
                    }
                }
            }

            if (kt + AT_TK > min_end_w) {
#pragma unroll
                for (int nt = 0; nt < 8; nt++) {
                    int k0 = kt + nt * 8 + (lane & 3) * 2;
                    if (k0 >= e0)     sacc[0][nt][0] = -1e30f;
                    if (k0 + 1 >= e0) sacc[0][nt][1] = -1e30f;
                    if (k0 >= e1)     sacc[0][nt][2] = -1e30f;
                    if (k0 + 1 >= e1) sacc[0][nt][3] = -1e30f;
                    if (k0 >= e2)     sacc[1][nt][0] = -1e30f;
                    if (k0 + 1 >= e2) sacc[1][nt][1] = -1e30f;
                    if (k0 >= e3)     sacc[1][nt][2] = -1e30f;
                    if (k0 + 1 >= e3) sacc[1][nt][3] = -1e30f;
                }
            }

            float tm0 = -1e30f, tm1 = -1e30f, tm2 = -1e30f, tm3 = -1e30f;
#pragma unroll
            for (int nt = 0; nt < 8; nt++) {
                tm0 = fmaxf(tm0, fmaxf(sacc[0][nt][0], sacc[0][nt][1]));
                tm1 = fmaxf(tm1, fmaxf(sacc[0][nt][2], sacc[0][nt][3]));
                tm2 = fmaxf(tm2, fmaxf(sacc[1][nt][0], sacc[1][nt][1]));
                tm3 = fmaxf(tm3, fmaxf(sacc[1][nt][2], sacc[1][nt][3]));
            }
            tm0 = fmaxf(tm0, __shfl_xor_sync(0xffffffffu, tm0, 1));
            tm0 = fmaxf(tm0, __shfl_xor_sync(0xffffffffu, tm0, 2));
            tm1 = fmaxf(tm1, __shfl_xor_sync(0xffffffffu, tm1, 1));
            tm1 = fmaxf(tm1, __shfl_xor_sync(0xffffffffu, tm1, 2));
            tm2 = fmaxf(tm2, __shfl_xor_sync(0xffffffffu, tm2, 1));
            tm2 = fmaxf(tm2, __shfl_xor_sync(0xffffffffu, tm2, 2));
            tm3 = fmaxf(tm3, __shfl_xor_sync(0xffffffffu, tm3, 1));
            tm3 = fmaxf(tm3, __shfl_xor_sync(0xffffffffu, tm3, 2));

            float mn0 = fmaxf(m0, tm0), mn1 = fmaxf(m1, tm1);
            float mn2 = fmaxf(m2, tm2), mn3 = fmaxf(m3, tm3);
            float c0 = exp2f(m0 - mn0), c1 = exp2f(m1 - mn1);
            float c2 = exp2f(m2 - mn2), c3 = exp2f(m3 - mn3);
            m0 = mn0; m1 = mn1; m2 = mn2; m3 = mn3;

#pragma unroll
            for (int dt = 0; dt < 8; dt++) {
                oacc[0][dt][0] *= c0; oacc[0][dt][1] *= c0;
                oacc[0][dt][2] *= c1; oacc[0][dt][3] *= c1;
                oacc[1][dt][0] *= c2; oacc[1][dt][1] *= c2;
                oacc[1][dt][2] *= c3; oacc[1][dt][3] *= c3;
            }

            float ts0 = 0.0f, ts1 = 0.0f, ts2 = 0.0f, ts3 = 0.0f;
#pragma unroll
            for (int g = 0; g < 8; g++) {
                if (kt + g * 8 < kend_w) {
                    float p00 = exp2f(sacc[0][g][0] - mn0);
                    float p01 = exp2f(sacc[0][g][1] - mn0);
                    float p02 = exp2f(sacc[0][g][2] - mn1);
                    float p03 = exp2f(sacc[0][g][3] - mn1);
                    float p10 = exp2f(sacc[1][g][0] - mn2);
                    float p11 = exp2f(sacc[1][g][1] - mn2);
                    float p12 = exp2f(sacc[1][g][2] - mn3);
                    float p13 = exp2f(sacc[1][g][3] - mn3);
                    ts0 += p00 + p01; ts1 += p02 + p03;
                    ts2 += p10 + p11; ts3 += p12 + p13;
                    uint4 ap0 = make_uint4(f2tf32(p00), f2tf32(p02), f2tf32(p01), f2tf32(p03));
                    uint4 ap1 = make_uint4(f2tf32(p10), f2tf32(p12), f2tf32(p11), f2tf32(p13));
#pragma unroll
                    for (int dt = 0; dt < 8; dt++) {
                        uint2 vf = *(const uint2*)&Vs[g][dt][(lane >> 2) ^ g][2 * (lane & 3)];
                        mma_tf32(oacc[0][dt], ap0, vf);
                        mma_tf32(oacc[1][dt], ap1, vf);
                    }
                }
            }
            ts0 += __shfl_xor_sync(0xffffffffu, ts0, 1);
            ts0 += __shfl_xor_sync(0xffffffffu, ts0, 2);
            ts1 += __shfl_xor_sync(0xffffffffu, ts1, 1);
            ts1 += __shfl_xor_sync(0xffffffffu, ts1, 2);
            ts2 += __shfl_xor_sync(0xffffffffu, ts2, 1);
            ts2 += __shfl_xor_sync(0xffffffffu, ts2, 2);
            ts3 += __shfl_xor_sync(0xffffffffu, ts3, 1);
            ts3 += __shfl_xor_sync(0xffffffffu, ts3, 2);
            l0 = l0 * c0 + ts0;
            l1 = l1 * c1 + ts1;
            l2 = l2 * c2 + ts2;
            l3 = l3 * c3 + ts3;
        }
        __syncthreads();
    }

    // epilogue: scatter into A-frag layout for GEMM3
    const float i0 = 1.0f / l0, i1 = 1.0f / l1, i2 = 1.0f / l2, i3 = 1.0f / l3;
    const int mb = b * T_SZ;
    const int col0 = h * DK_SZ + (lane & 3) * 2;
#pragma unroll
    for (int dt = 0; dt < 8; dt++) {
        int c = col0 + dt * 8;
        st_frag(outf, mb + qa,      c,     oacc[0][dt][0] * i0);
        st_frag(outf, mb + qa,      c + 1, oacc[0][dt][1] * i0);
        st_frag(outf, mb + qa + 8,  c,     oacc[0][dt][2] * i1);
        st_frag(outf, mb + qa + 8,  c + 1, oacc[0][dt][3] * i1);
        st_frag(outf, mb + qa + 16, c,     oacc[1][dt][0] * i2);
        st_frag(outf, mb + qa + 16, c + 1, oacc[1][dt][1] * i2);
        st_frag(outf, mb + qa + 24, c,     oacc[1][dt][2] * i3);
        st_frag(outf, mb + qa + 24, c + 1, oacc[1][dt][3] * i3);
    }
}

// ---------------------------------------------------------------------------
// launch
// ---------------------------------------------------------------------------
extern "C" void kernel_launch(void* const* d_in, const int* in_sizes, int n_in,
                              void* d_out, int out_size) {
    const float* x = (const float*)d_in[0];
    const int* prefix_raw = (const int*)d_in[1];
    const float* W_qkv = (const float*)d_in[2];
    const float* W_o = (const float*)d_in[3];
    float* out = (float*)d_out;

    float* qkv = nullptr;
    unsigned *xf = nullptr, *wqf = nullptr, *wof = nullptr, *af = nullptr;
    cudaGetSymbolAddress((void**)&qkv, g_qkv);
    cudaGetSymbolAddress((void**)&xf, g_xfrag);
    cudaGetSymbolAddress((void**)&wqf, g_wqkvfrag);
    cudaGetSymbolAddress((void**)&wof, g_wofrag);
    cudaGetSymbolAddress((void**)&af, g_attnfrag);

    const int M = B_SZ * T_SZ;  // 8192

    decode_prefix_kernel<<<1, 1>>>(prefix_raw);

    // 0) operand prep into fragment layouts
    {
        int nx = M * D_SZ / 4;          // 2,097,152
        prep_afrag<<<nx / 256, 256>>>(x, (uint4*)xf, D_SZ, nx);
        int nq = D3 * D_SZ / 4;         // 786,432
        prep_bfrag<<<nq / 256, 256>>>(W_qkv, (uint4*)wqf, D_SZ, nq);
        int no = D_SZ * D_SZ / 4;       // 262,144
        prep_bfrag<<<no / 256, 256>>>(W_o, (uint4*)wof, D_SZ, no);
    }

    // 1) qkv = x @ W_qkv^T   [8192, 3072]
    {
        dim3 grid(D3 / 128, M / 128);
        gemm_frag_nt<<<grid, 128>>>((const uint4*)xf, (const uint4*)wqf, qkv, M, D3, D_SZ);
    }

    // 2) attention -> g_attnfrag (A-frag layout)
    {
        dim3 grid(T_SZ / AT_TQ, H_SZ, B_SZ);
        attn_mma_kernel<<<grid, 256>>>(qkv, af);
    }

    // 3) out = attn @ W_o^T  [8192, 1024]
    {
        dim3 grid(D_SZ / 128, M / 128);
        gemm_frag_nt<<<grid, 128>>>((const uint4*)af, (const uint4*)wof, out, M, D_SZ, D_SZ);
    }
}

// round 15
// speedup vs baseline: 8.4540x; 1.1127x over previous
#include <cuda_runtime.h>
#include <cuda_bf16.h>
#include <math.h>
#include <stdint.h>

// Problem constants
#define B_SZ 4
#define T_SZ 2048
#define D_SZ 1024
#define H_SZ 16
#define DK_SZ 64
#define D3 (3 * D_SZ)

// Scratch (device globals; no allocation allowed)
__device__ __align__(16) float g_qkv[(size_t)B_SZ * T_SZ * D3];           // 96 MB row-major
__device__ __align__(16) unsigned g_attnfrag[(size_t)B_SZ * T_SZ * D_SZ]; // A-frag tf32
__device__ __align__(16) unsigned g_xfrag[(size_t)B_SZ * T_SZ * D_SZ];    // A-frag tf32
__device__ __align__(16) unsigned g_wqkvfrag[(size_t)D3 * D_SZ];          // B-frag tf32
__device__ __align__(16) unsigned g_wofrag[(size_t)D_SZ * D_SZ];          // B-frag tf32
__device__ int g_prefix[B_SZ];

// ---------------------------------------------------------------------------
// Prefix decode (robust to int32 or int64 storage).
// ---------------------------------------------------------------------------
__global__ void decode_prefix_kernel(const int* __restrict__ raw) {
    bool is64 = (raw[1] == 0) && (raw[3] == 0);
    for (int b = 0; b < B_SZ; b++) {
        int p = is64 ? raw[2 * b] : raw[b];
        if (p < 0) p = 0;
        if (p > T_SZ) p = T_SZ;
        g_prefix[b] = p;
    }
}

// ---------------------------------------------------------------------------
// tf32 helpers
// ---------------------------------------------------------------------------
__device__ __forceinline__ unsigned f2tf32(float v) {
    unsigned u;
    asm("cvt.rna.tf32.f32 %0, %1;" : "=r"(u) : "f"(v));
    return u;
}

__device__ __forceinline__ void mma_tf32(float* c, const uint4& a, const uint2& b) {
    asm volatile(
        "mma.sync.aligned.m16n8k8.row.col.f32.tf32.tf32.f32 "
        "{%0,%1,%2,%3}, {%4,%5,%6,%7}, {%8,%9}, {%0,%1,%2,%3};"
        : "+f"(c[0]), "+f"(c[1]), "+f"(c[2]), "+f"(c[3])
        : "r"(a.x), "r"(a.y), "r"(a.z), "r"(a.w), "r"(b.x), "r"(b.y));
}

#define CP_ASYNC16(saddr, gptr) \
    asm volatile("cp.async.cg.shared.global [%0], [%1], 16;" :: "r"(saddr), "l"(gptr))
#define CP_COMMIT() asm volatile("cp.async.commit_group;" ::: "memory")
#define CP_WAIT1()  asm volatile("cp.async.wait_group 1;" ::: "memory")

// ===========================================================================
// Fragment-layout gmem format (matches smem blocks exactly) — see round 14.
// ===========================================================================
__global__ void prep_afrag(const float* __restrict__ A, uint4* __restrict__ dst,
                           int K, int nU4) {
    int U = blockIdx.x * 256 + threadIdx.x;
    if (U >= nU4) return;
    int K16 = K >> 4;
    int perRb = K16 * 512;
    int rb = U / perRb, rem = U % perRb;
    int it = rem >> 9, u = rem & 511;
    int ks = u >> 8, mt = (u >> 5) & 7, lane = u & 31;
    int r = rb * 128 + mt * 16 + (lane >> 2);
    int k = it * 16 + ks * 8 + (lane & 3);
    const float* p = A + (size_t)r * K + k;
    uint4 o;
    o.x = f2tf32(p[0]);
    o.y = f2tf32(p[(size_t)8 * K]);
    o.z = f2tf32(p[4]);
    o.w = f2tf32(p[(size_t)8 * K + 4]);
    dst[U] = o;
}

__global__ void prep_bfrag(const float* __restrict__ Bm, uint4* __restrict__ dst,
                           int K, int nU4) {
    int U = blockIdx.x * 256 + threadIdx.x;
    if (U >= nU4) return;
    int K16 = K >> 4;
    int perCb = K16 * 512;
    int cb = U / perCb, rem = U % perCb;
    int it = rem >> 9, u = rem & 511;
    int ks = u >> 8;
    int q = u & 255;
    int nt = q >> 4;
    int lane0 = (q << 1) & 31;
    int n = cb * 128 + nt * 8 + (lane0 >> 2);
    int k = it * 16 + ks * 8 + (lane0 & 3);
    const float* p = Bm + (size_t)n * K + k;
    uint4 o;
    o.x = f2tf32(p[0]);
    o.y = f2tf32(p[4]);
    o.z = f2tf32(p[1]);
    o.w = f2tf32(p[5]);
    dst[U] = o;
}

// scatter one fp32 value into A-frag layout (K fixed = 1024 -> K16 = 64)
__device__ __forceinline__ void st_frag(unsigned* dst, int m, int k, float v) {
    size_t w = ((size_t)(m >> 7) * 64 + (k >> 4)) * 2048
             + (size_t)(((k >> 3) & 1) * 1024)
             + (size_t)(((m & 127) >> 4) * 128)
             + (size_t)(((((m & 7) << 2) | (k & 3))) * 4)
             + (size_t)(((m >> 3) & 1) + (((k >> 2) & 1) << 1));
    dst[w] = f2tf32(v);
}

// ===========================================================================
// GEMM from fragment-layout operands: C = A @ B^T (fp32 out, row-major).
// Block 128x128, BK=16, 128 threads = 4 warps (2x2, warp tile 64x64).
// 3-stage cp.async pipeline; target 3 blocks/SM.
// ===========================================================================
#define GSTAGES 3

__global__ __launch_bounds__(128, 3)
void gemm_frag_nt(const uint4* __restrict__ Af, const uint4* __restrict__ Bf,
                  float* __restrict__ C, int M, int N, int K) {
    __shared__ uint4 As[GSTAGES][512];   // 8KB/stage
    __shared__ uint4 Bs[GSTAGES][512];

    const int tid = threadIdx.x;
    const int warp = tid >> 5;
    const int lane = tid & 31;
    const int wm = warp >> 1;
    const int wn = warp & 1;
    const int K16 = K >> 4;

    const uint4* ab = Af + (size_t)blockIdx.y * K16 * 512 + tid;
    const uint4* bb = Bf + (size_t)blockIdx.x * K16 * 512 + tid;

    float acc[4][8][4];
#pragma unroll
    for (int i = 0; i < 4; i++)
#pragma unroll
        for (int j = 0; j < 8; j++)
#pragma unroll
            for (int c = 0; c < 4; c++) acc[i][j][c] = 0.0f;

    // prologue: fill stages 0..GSTAGES-2
#pragma unroll
    for (int s = 0; s < GSTAGES - 1; s++) {
#pragma unroll
        for (int j = 0; j < 4; j++) {
            uint32_t sa = (uint32_t)__cvta_generic_to_shared(&As[s][tid + j * 128]);
            uint32_t sb = (uint32_t)__cvta_generic_to_shared(&Bs[s][tid + j * 128]);
            CP_ASYNC16(sa, ab + (size_t)s * 512 + j * 128);
            CP_ASYNC16(sb, bb + (size_t)s * 512 + j * 128);
        }
        CP_COMMIT();
    }
    CP_WAIT1();  // stage 0 resident
    __syncthreads();

    for (int it = 0; it < K16; it++) {
        const int buf = it % GSTAGES;

        // issue fill for it+GSTAGES-1 (slot reuse is safe: its last compute
        // finished before the __syncthreads at the end of iter it-1)
        if (it + GSTAGES - 1 < K16) {
            const int s = (it + GSTAGES - 1) % GSTAGES;
            const size_t base = (size_t)(it + GSTAGES - 1) * 512;
#pragma unroll
            for (int j = 0; j < 4; j++) {
                uint32_t sa = (uint32_t)__cvta_generic_to_shared(&As[s][tid + j * 128]);
                uint32_t sb = (uint32_t)__cvta_generic_to_shared(&Bs[s][tid + j * 128]);
                CP_ASYNC16(sa, ab + base + j * 128);
                CP_ASYNC16(sb, bb + base + j * 128);
            }
        }
        CP_COMMIT();

        const unsigned* Au = (const unsigned*)As[buf];
        const unsigned* Bu = (const unsigned*)Bs[buf];
#pragma unroll
        for (int ks = 0; ks < 2; ks++) {
            uint4 af[4];
            uint2 bf[8];
#pragma unroll
            for (int mt = 0; mt < 4; mt++)
                af[mt] = *(const uint4*)&Au[(ks * 8 + wm * 4 + mt) * 128 + lane * 4];
#pragma unroll
            for (int nt = 0; nt < 8; nt++)
                bf[nt] = *(const uint2*)&Bu[(ks * 16 + wn * 8 + nt) * 64 + lane * 2];
#pragma unroll
            for (int mt = 0; mt < 4; mt++)
#pragma unroll
                for (int nt = 0; nt < 8; nt++)
                    mma_tf32(acc[mt][nt], af[mt], bf[nt]);
        }

        CP_WAIT1();     // next stage resident
        __syncthreads();
    }

    const int r_base = blockIdx.y * 128 + wm * 64 + (lane >> 2);
    const int c_base = blockIdx.x * 128 + wn * 64 + (lane & 3) * 2;
#pragma unroll
    for (int mt = 0; mt < 4; mt++) {
#pragma unroll
        for (int nt = 0; nt < 8; nt++) {
            int r = r_base + mt * 16;
            int c = c_base + nt * 8;
            *(float2*)&C[(size_t)r * N + c] =
                make_float2(acc[mt][nt][0], acc[mt][nt][1]);
            *(float2*)&C[(size_t)(r + 8) * N + c] =
                make_float2(acc[mt][nt][2], acc[mt][nt][3]);
        }
    }
}

// ---------------------------------------------------------------------------
// Tensor-core flash attention (prefix-LM mask). 256 queries/block, 32/warp.
// Epilogue writes O directly in A-frag layout (tf32) for GEMM3.
// ---------------------------------------------------------------------------
#define AT_TQ 256
#define AT_TK 64

__global__ __launch_bounds__(256, 1)
void attn_mma_kernel(const float* __restrict__ qkv, unsigned* __restrict__ outf) {
    __shared__ unsigned Ks[8][8][32][2];
    __shared__ unsigned Vs[8][8][8][8];

    const int b = blockIdx.z;
    const int h = blockIdx.y;
    const int q0 = blockIdx.x * AT_TQ;
    const int tid = threadIdx.x;
    const int warp = tid >> 5;
    const int lane = tid & 31;

    const int P = g_prefix[b];

    const int q0w = q0 + warp * 32;
    const int qa = q0w + (lane >> 2);
    const int qc = qa + 16;
    const int e0 = (qa < P) ? P : (qa + 1);
    const int e1 = (qa + 8 < P) ? P : (qa + 9);
    const int e2 = (qc < P) ? P : (qc + 1);
    const int e3 = (qc + 8 < P) ? P : (qc + 9);
    const int min_end_w = (q0w < P) ? P : (q0w + 1);

    int kend_w = q0w + 32;
    if (P > kend_w) kend_w = P;
    if (kend_w > T_SZ) kend_w = T_SZ;
    int kend = q0 + AT_TQ;
    if (P > kend) kend = P;
    if (kend > T_SZ) kend = T_SZ;

    const float qscale = 0.125f * 1.4426950408889634f;
    uint4 aq[8][2];
    {
        const int c = lane & 3;
        const float* q0p = qkv + (size_t)(b * T_SZ + qa) * D3 + h * DK_SZ;
        const float* q1p = q0p + (size_t)8 * D3;
        const float* q2p = q0p + (size_t)16 * D3;
        const float* q3p = q0p + (size_t)24 * D3;
#pragma unroll
        for (int g = 0; g < 8; g++) {
            aq[g][0].x = f2tf32(q0p[g * 8 + c] * qscale);
            aq[g][0].y = f2tf32(q1p[g * 8 + c] * qscale);
            aq[g][0].z = f2tf32(q0p[g * 8 + c + 4] * qscale);
            aq[g][0].w = f2tf32(q1p[g * 8 + c + 4] * qscale);
            aq[g][1].x = f2tf32(q2p[g * 8 + c] * qscale);
            aq[g][1].y = f2tf32(q3p[g * 8 + c] * qscale);
            aq[g][1].z = f2tf32(q2p[g * 8 + c + 4] * qscale);
            aq[g][1].w = f2tf32(q3p[g * 8 + c + 4] * qscale);
        }
    }

    float oacc[2][8][4];
#pragma unroll
    for (int mf = 0; mf < 2; mf++)
#pragma unroll
        for (int dt = 0; dt < 8; dt++)
#pragma unroll
            for (int e = 0; e < 4; e++) oacc[mf][dt][e] = 0.0f;
    float m0 = -1e30f, m1 = -1e30f, m2 = -1e30f, m3 = -1e30f;
    float l0 = 0.0f, l1 = 0.0f, l2 = 0.0f, l3 = 0.0f;

    for (int kt = 0; kt < kend; kt += AT_TK) {
#pragma unroll
        for (int cc = 0; cc < 2; cc++) {
            int c = tid + cc * 256;
            int j = c & 63;
            int ds = c >> 6;
            const float* kr = qkv + (size_t)(b * T_SZ + kt + j) * D3 + D_SZ + h * DK_SZ + ds * 8;
            float4 lo = *(const float4*)(kr);
            float4 hi = *(const float4*)(kr + 4);
            int p = (j & 7) * 4;
            *(uint4*)&Ks[ds][j >> 3][p][0] =
                make_uint4(f2tf32(lo.x), f2tf32(hi.x), f2tf32(lo.y), f2tf32(hi.y));
            *(uint4*)&Ks[ds][j >> 3][p + 2][0] =
                make_uint4(f2tf32(lo.z), f2tf32(hi.z), f2tf32(lo.w), f2tf32(hi.w));
        }
#pragma unroll
        for (int cc = 0; cc < 2; cc++) {
            int c = tid + cc * 256;
            int j = c & 63;
            int dstep = c >> 6;
            const float* vr = qkv + (size_t)(b * T_SZ + kt + j) * D3 + 2 * D_SZ + h * DK_SZ + dstep * 8;
            float4 lo = *(const float4*)(vr);
            float4 hi = *(const float4*)(vr + 4);
            int g = j >> 3, jk = j & 7;
            Vs[g][dstep][0 ^ g][jk] = f2tf32(lo.x);
            Vs[g][dstep][1 ^ g][jk] = f2tf32(lo.y);
            Vs[g][dstep][2 ^ g][jk] = f2tf32(lo.z);
            Vs[g][dstep][3 ^ g][jk] = f2tf32(lo.w);
            Vs[g][dstep][4 ^ g][jk] = f2tf32(hi.x);
            Vs[g][dstep][5 ^ g][jk] = f2tf32(hi.y);
            Vs[g][dstep][6 ^ g][jk] = f2tf32(hi.z);
            Vs[g][dstep][7 ^ g][jk] = f2tf32(hi.w);
        }
        __syncthreads();

        if (kt < kend_w) {
            float sacc[2][8][4];
#pragma unroll
            for (int mf = 0; mf < 2; mf++)
#pragma unroll
                for (int nt = 0; nt < 8; nt++)
#pragma unroll
                    for (int e = 0; e < 4; e++) sacc[mf][nt][e] = 0.0f;

#pragma unroll
            for (int nt = 0; nt < 8; nt++) {
                if (kt + nt * 8 < kend_w) {
#pragma unroll
                    for (int g = 0; g < 8; g++) {
                        uint2 bf = *(const uint2*)&Ks[g][nt][lane][0];
                        mma_tf32(sacc[0][nt], aq[g][0], bf);
                        mma_tf32(sacc[1][nt], aq[g][1], bf);
                    }
                }
            }

            if (kt + AT_TK > min_end_w) {
#pragma unroll
                for (int nt = 0; nt < 8; nt++) {
                    int k0 = kt + nt * 8 + (lane & 3) * 2;
                    if (k0 >= e0)     sacc[0][nt][0] = -1e30f;
                    if (k0 + 1 >= e0) sacc[0][nt][1] = -1e30f;
                    if (k0 >= e1)     sacc[0][nt][2] = -1e30f;
                    if (k0 + 1 >= e1) sacc[0][nt][3] = -1e30f;
                    if (k0 >= e2)     sacc[1][nt][0] = -1e30f;
                    if (k0 + 1 >= e2) sacc[1][nt][1] = -1e30f;
                    if (k0 >= e3)     sacc[1][nt][2] = -1e30f;
                    if (k0 + 1 >= e3) sacc[1][nt][3] = -1e30f;
                }
            }

            float tm0 = -1e30f, tm1 = -1e30f, tm2 = -1e30f, tm3 = -1e30f;
#pragma unroll
            for (int nt = 0; nt < 8; nt++) {
                tm0 = fmaxf(tm0, fmaxf(sacc[0][nt][0], sacc[0][nt][1]));
                tm1 = fmaxf(tm1, fmaxf(sacc[0][nt][2], sacc[0][nt][3]));
                tm2 = fmaxf(tm2, fmaxf(sacc[1][nt][0], sacc[1][nt][1]));
                tm3 = fmaxf(tm3, fmaxf(sacc[1][nt][2], sacc[1][nt][3]));
            }
            tm0 = fmaxf(tm0, __shfl_xor_sync(0xffffffffu, tm0, 1));
            tm0 = fmaxf(tm0, __shfl_xor_sync(0xffffffffu, tm0, 2));
            tm1 = fmaxf(tm1, __shfl_xor_sync(0xffffffffu, tm1, 1));
            tm1 = fmaxf(tm1, __shfl_xor_sync(0xffffffffu, tm1, 2));
            tm2 = fmaxf(tm2, __shfl_xor_sync(0xffffffffu, tm2, 1));
            tm2 = fmaxf(tm2, __shfl_xor_sync(0xffffffffu, tm2, 2));
            tm3 = fmaxf(tm3, __shfl_xor_sync(0xffffffffu, tm3, 1));
            tm3 = fmaxf(tm3, __shfl_xor_sync(0xffffffffu, tm3, 2));

            float mn0 = fmaxf(m0, tm0), mn1 = fmaxf(m1, tm1);
            float mn2 = fmaxf(m2, tm2), mn3 = fmaxf(m3, tm3);
            float c0 = exp2f(m0 - mn0), c1 = exp2f(m1 - mn1);
            float c2 = exp2f(m2 - mn2), c3 = exp2f(m3 - mn3);
            m0 = mn0; m1 = mn1; m2 = mn2; m3 = mn3;

#pragma unroll
            for (int dt = 0; dt < 8; dt++) {
                oacc[0][dt][0] *= c0; oacc[0][dt][1] *= c0;
                oacc[0][dt][2] *= c1; oacc[0][dt][3] *= c1;
                oacc[1][dt][0] *= c2; oacc[1][dt][1] *= c2;
                oacc[1][dt][2] *= c3; oacc[1][dt][3] *= c3;
            }

            float ts0 = 0.0f, ts1 = 0.0f, ts2 = 0.0f, ts3 = 0.0f;
#pragma unroll
            for (int g = 0; g < 8; g++) {
                if (kt + g * 8 < kend_w) {
                    float p00 = exp2f(sacc[0][g][0] - mn0);
                    float p01 = exp2f(sacc[0][g][1] - mn0);
                    float p02 = exp2f(sacc[0][g][2] - mn1);
                    float p03 = exp2f(sacc[0][g][3] - mn1);
                    float p10 = exp2f(sacc[1][g][0] - mn2);
                    float p11 = exp2f(sacc[1][g][1] - mn2);
                    float p12 = exp2f(sacc[1][g][2] - mn3);
                    float p13 = exp2f(sacc[1][g][3] - mn3);
                    ts0 += p00 + p01; ts1 += p02 + p03;
                    ts2 += p10 + p11; ts3 += p12 + p13;
                    uint4 ap0 = make_uint4(f2tf32(p00), f2tf32(p02), f2tf32(p01), f2tf32(p03));
                    uint4 ap1 = make_uint4(f2tf32(p10), f2tf32(p12), f2tf32(p11), f2tf32(p13));
#pragma unroll
                    for (int dt = 0; dt < 8; dt++) {
                        uint2 vf = *(const uint2*)&Vs[g][dt][(lane >> 2) ^ g][2 * (lane & 3)];
                        mma_tf32(oacc[0][dt], ap0, vf);
                        mma_tf32(oacc[1][dt], ap1, vf);
                    }
                }
            }
            ts0 += __shfl_xor_sync(0xffffffffu, ts0, 1);
            ts0 += __shfl_xor_sync(0xffffffffu, ts0, 2);
            ts1 += __shfl_xor_sync(0xffffffffu, ts1, 1);
            ts1 += __shfl_xor_sync(0xffffffffu, ts1, 2);
            ts2 += __shfl_xor_sync(0xffffffffu, ts2, 1);
            ts2 += __shfl_xor_sync(0xffffffffu, ts2, 2);
            ts3 += __shfl_xor_sync(0xffffffffu, ts3, 1);
            ts3 += __shfl_xor_sync(0xffffffffu, ts3, 2);
            l0 = l0 * c0 + ts0;
            l1 = l1 * c1 + ts1;
            l2 = l2 * c2 + ts2;
            l3 = l3 * c3 + ts3;
        }
        __syncthreads();
    }

    // epilogue: scatter into A-frag layout for GEMM3
    const float i0 = 1.0f / l0, i1 = 1.0f / l1, i2 = 1.0f / l2, i3 = 1.0f / l3;
    const int mb = b * T_SZ;
    const int col0 = h * DK_SZ + (lane & 3) * 2;
#pragma unroll
    for (int dt = 0; dt < 8; dt++) {
        int c = col0 + dt * 8;
        st_frag(outf, mb + qa,      c,     oacc[0][dt][0] * i0);
        st_frag(outf, mb + qa,      c + 1, oacc[0][dt][1] * i0);
        st_frag(outf, mb + qa + 8,  c,     oacc[0][dt][2] * i1);
        st_frag(outf, mb + qa + 8,  c + 1, oacc[0][dt][3] * i1);
        st_frag(outf, mb + qa + 16, c,     oacc[1][dt][0] * i2);
        st_frag(outf, mb + qa + 16, c + 1, oacc[1][dt][1] * i2);
        st_frag(outf, mb + qa + 24, c,     oacc[1][dt][2] * i3);
        st_frag(outf, mb + qa + 24, c + 1, oacc[1][dt][3] * i3);
    }
}

// ---------------------------------------------------------------------------
// launch
// ---------------------------------------------------------------------------
extern "C" void kernel_launch(void* const* d_in, const int* in_sizes, int n_in,
                              void* d_out, int out_size) {
    const float* x = (const float*)d_in[0];
    const int* prefix_raw = (const int*)d_in[1];
    const float* W_qkv = (const float*)d_in[2];
    const float* W_o = (const float*)d_in[3];
    float* out = (float*)d_out;

    float* qkv = nullptr;
    unsigned *xf = nullptr, *wqf = nullptr, *wof = nullptr, *af = nullptr;
    cudaGetSymbolAddress((void**)&qkv, g_qkv);
    cudaGetSymbolAddress((void**)&xf, g_xfrag);
    cudaGetSymbolAddress((void**)&wqf, g_wqkvfrag);
    cudaGetSymbolAddress((void**)&wof, g_wofrag);
    cudaGetSymbolAddress((void**)&af, g_attnfrag);

    const int M = B_SZ * T_SZ;  // 8192

    decode_prefix_kernel<<<1, 1>>>(prefix_raw);

    // 0) operand prep into fragment layouts
    {
        int nx = M * D_SZ / 4;
        prep_afrag<<<nx / 256, 256>>>(x, (uint4*)xf, D_SZ, nx);
        int nq = D3 * D_SZ / 4;
        prep_bfrag<<<nq / 256, 256>>>(W_qkv, (uint4*)wqf, D_SZ, nq);
        int no = D_SZ * D_SZ / 4;
        prep_bfrag<<<no / 256, 256>>>(W_o, (uint4*)wof, D_SZ, no);
    }

    // 1) qkv = x @ W_qkv^T   [8192, 3072]
    {
        dim3 grid(D3 / 128, M / 128);
        gemm_frag_nt<<<grid, 128>>>((const uint4*)xf, (const uint4*)wqf, qkv, M, D3, D_SZ);
    }

    // 2) attention -> g_attnfrag (A-frag layout)
    {
        dim3 grid(T_SZ / AT_TQ, H_SZ, B_SZ);
        attn_mma_kernel<<<grid, 256>>>(qkv, af);
    }

    // 3) out = attn @ W_o^T  [8192, 1024]
    {
        dim3 grid(D_SZ / 128, M / 128);
        gemm_frag_nt<<<grid, 128>>>((const uint4*)af, (const uint4*)wof, out, M, D_SZ, D_SZ);
    }
}

// round 16
// speedup vs baseline: 9.6461x; 1.1410x over previous
#include <cuda_runtime.h>
#include <cuda_bf16.h>
#include <math.h>
#include <stdint.h>

// Problem constants
#define B_SZ 4
#define T_SZ 2048
#define D_SZ 1024
#define H_SZ 16
#define DK_SZ 64
#define D3 (3 * D_SZ)

// Scratch (device globals; no allocation allowed)
__device__ __align__(16) float g_qkv[(size_t)B_SZ * T_SZ * D3];           // 96 MB row-major
__device__ __align__(16) unsigned g_attnfrag[(size_t)B_SZ * T_SZ * D_SZ]; // A-frag tf32
__device__ __align__(16) unsigned g_xfrag[(size_t)B_SZ * T_SZ * D_SZ];    // A-frag tf32
__device__ __align__(16) unsigned g_wqkvfrag[(size_t)D3 * D_SZ];          // B-frag tf32
__device__ __align__(16) unsigned g_wofrag[(size_t)D_SZ * D_SZ];          // B-frag tf32
__device__ __align__(16) unsigned g_kfrag[(size_t)B_SZ * H_SZ * 32 * 4096]; // Ks-layout tf32
__device__ __align__(16) unsigned g_vfrag[(size_t)B_SZ * H_SZ * 32 * 4096]; // Vs-layout tf32
__device__ int g_prefix[B_SZ];

// ---------------------------------------------------------------------------
// Prefix decode (robust to int32 or int64 storage).
// ---------------------------------------------------------------------------
__global__ void decode_prefix_kernel(const int* __restrict__ raw) {
    bool is64 = (raw[1] == 0) && (raw[3] == 0);
    for (int b = 0; b < B_SZ; b++) {
        int p = is64 ? raw[2 * b] : raw[b];
        if (p < 0) p = 0;
        if (p > T_SZ) p = T_SZ;
        g_prefix[b] = p;
    }
}

// ---------------------------------------------------------------------------
// tf32 / math helpers
// ---------------------------------------------------------------------------
__device__ __forceinline__ unsigned f2tf32(float v) {
    unsigned u;
    asm("cvt.rna.tf32.f32 %0, %1;" : "=r"(u) : "f"(v));
    return u;
}

__device__ __forceinline__ float ex2(float x) {
    float y;
    asm("ex2.approx.ftz.f32 %0, %1;" : "=f"(y) : "f"(x));
    return y;
}

__device__ __forceinline__ void mma_tf32(float* c, const uint4& a, const uint2& b) {
    asm volatile(
        "mma.sync.aligned.m16n8k8.row.col.f32.tf32.tf32.f32 "
        "{%0,%1,%2,%3}, {%4,%5,%6,%7}, {%8,%9}, {%0,%1,%2,%3};"
        : "+f"(c[0]), "+f"(c[1]), "+f"(c[2]), "+f"(c[3])
        : "r"(a.x), "r"(a.y), "r"(a.z), "r"(a.w), "r"(b.x), "r"(b.y));
}

#define CP_ASYNC16(saddr, gptr) \
    asm volatile("cp.async.cg.shared.global [%0], [%1], 16;" :: "r"(saddr), "l"(gptr))
#define CP_COMMIT() asm volatile("cp.async.commit_group;" ::: "memory")
#define CP_WAIT1()  asm volatile("cp.async.wait_group 1;" ::: "memory")
#define CP_WAIT0()  asm volatile("cp.async.wait_group 0;" ::: "memory")

// ===========================================================================
// Fragment-layout preps (GEMM operands) — see round 14.
// ===========================================================================
__global__ void prep_afrag(const float* __restrict__ A, uint4* __restrict__ dst,
                           int K, int nU4) {
    int U = blockIdx.x * 256 + threadIdx.x;
    if (U >= nU4) return;
    int K16 = K >> 4;
    int perRb = K16 * 512;
    int rb = U / perRb, rem = U % perRb;
    int it = rem >> 9, u = rem & 511;
    int ks = u >> 8, mt = (u >> 5) & 7, lane = u & 31;
    int r = rb * 128 + mt * 16 + (lane >> 2);
    int k = it * 16 + ks * 8 + (lane & 3);
    const float* p = A + (size_t)r * K + k;
    uint4 o;
    o.x = f2tf32(p[0]);
    o.y = f2tf32(p[(size_t)8 * K]);
    o.z = f2tf32(p[4]);
    o.w = f2tf32(p[(size_t)8 * K + 4]);
    dst[U] = o;
}

__global__ void prep_bfrag(const float* __restrict__ Bm, uint4* __restrict__ dst,
                           int K, int nU4) {
    int U = blockIdx.x * 256 + threadIdx.x;
    if (U >= nU4) return;
    int K16 = K >> 4;
    int perCb = K16 * 512;
    int cb = U / perCb, rem = U % perCb;
    int it = rem >> 9, u = rem & 511;
    int ks = u >> 8;
    int q = u & 255;
    int nt = q >> 4;
    int lane0 = (q << 1) & 31;
    int n = cb * 128 + nt * 8 + (lane0 >> 2);
    int k = it * 16 + ks * 8 + (lane0 & 3);
    const float* p = Bm + (size_t)n * K + k;
    uint4 o;
    o.x = f2tf32(p[0]);
    o.y = f2tf32(p[4]);
    o.z = f2tf32(p[1]);
    o.w = f2tf32(p[5]);
    dst[U] = o;
}

// ===========================================================================
// Attention K/V fragment preps. Layouts match the smem Ks/Vs arrays exactly:
//   K word = ds*512 + jt*64 + lane*2 + slot ; elem K[key=jt*8+(lane>>2)]
//            [dk = ds*8 + (lane&3) + 4*slot]
//   V word = g*512 + dt*64 + (i^g)*8 + jk  ; elem V[key=g*8+jk][dk=dt*8+i]
// One uint4 (4 words) per thread. Per (b,h,ktile): 1024 quads.
// ===========================================================================
__global__ void prep_kfrag(const float* __restrict__ qkv, uint4* __restrict__ dst,
                           int nU4) {
    int U = blockIdx.x * 256 + threadIdx.x;
    if (U >= nU4) return;
    int bh = U >> 15;               // / (32*1024)
    int rem = U & 32767;
    int ktile = rem >> 10;
    int u = rem & 1023;
    int ds = u >> 7;
    int jt = (u >> 4) & 7;
    int l0 = (u & 15) << 1;         // even lane
    int b = bh >> 4, h = bh & 15;
    int key = ktile * 64 + jt * 8 + (l0 >> 2);
    int c0 = l0 & 3;                // 0 or 2
    const float* p = qkv + (size_t)(b * T_SZ + key) * D3 + D_SZ + h * DK_SZ + ds * 8 + c0;
    uint4 o;
    o.x = f2tf32(p[0]);
    o.y = f2tf32(p[4]);
    o.z = f2tf32(p[1]);
    o.w = f2tf32(p[5]);
    dst[U] = o;
}

__global__ void prep_vfrag(const float* __restrict__ qkv, uint4* __restrict__ dst,
                           int nU4) {
    int U = blockIdx.x * 256 + threadIdx.x;
    if (U >= nU4) return;
    int bh = U >> 15;
    int rem = U & 32767;
    int ktile = rem >> 10;
    int u = rem & 1023;
    int g = u >> 7;
    int dt = (u >> 4) & 7;
    int row = (u >> 1) & 7;
    int jk0 = (u & 1) << 2;
    int i = row ^ g;                // dk within octet
    int b = bh >> 4, h = bh & 15;
    int key = ktile * 64 + g * 8 + jk0;
    const float* p = qkv + (size_t)(b * T_SZ + key) * D3 + 2 * D_SZ + h * DK_SZ + dt * 8 + i;
    uint4 o;
    o.x = f2tf32(p[0]);
    o.y = f2tf32(p[(size_t)D3]);
    o.z = f2tf32(p[(size_t)2 * D3]);
    o.w = f2tf32(p[(size_t)3 * D3]);
    dst[U] = o;
}

// scatter one fp32 value into A-frag layout (K fixed = 1024 -> K16 = 64)
__device__ __forceinline__ void st_frag(unsigned* dst, int m, int k, float v) {
    size_t w = ((size_t)(m >> 7) * 64 + (k >> 4)) * 2048
             + (size_t)(((k >> 3) & 1) * 1024)
             + (size_t)(((m & 127) >> 4) * 128)
             + (size_t)(((((m & 7) << 2) | (k & 3))) * 4)
             + (size_t)(((m >> 3) & 1) + (((k >> 2) & 1) << 1));
    dst[w] = f2tf32(v);
}

// ===========================================================================
// GEMM from fragment-layout operands (round 15, unchanged).
// ===========================================================================
#define GSTAGES 3

__global__ __launch_bounds__(128, 3)
void gemm_frag_nt(const uint4* __restrict__ Af, const uint4* __restrict__ Bf,
                  float* __restrict__ C, int M, int N, int K) {
    __shared__ uint4 As[GSTAGES][512];
    __shared__ uint4 Bs[GSTAGES][512];

    const int tid = threadIdx.x;
    const int warp = tid >> 5;
    const int lane = tid & 31;
    const int wm = warp >> 1;
    const int wn = warp & 1;
    const int K16 = K >> 4;

    const uint4* ab = Af + (size_t)blockIdx.y * K16 * 512 + tid;
    const uint4* bb = Bf + (size_t)blockIdx.x * K16 * 512 + tid;

    float acc[4][8][4];
#pragma unroll
    for (int i = 0; i < 4; i++)
#pragma unroll
        for (int j = 0; j < 8; j++)
#pragma unroll
            for (int c = 0; c < 4; c++) acc[i][j][c] = 0.0f;

#pragma unroll
    for (int s = 0; s < GSTAGES - 1; s++) {
#pragma unroll
        for (int j = 0; j < 4; j++) {
            uint32_t sa = (uint32_t)__cvta_generic_to_shared(&As[s][tid + j * 128]);
            uint32_t sb = (uint32_t)__cvta_generic_to_shared(&Bs[s][tid + j * 128]);
            CP_ASYNC16(sa, ab + (size_t)s * 512 + j * 128);
            CP_ASYNC16(sb, bb + (size_t)s * 512 + j * 128);
        }
        CP_COMMIT();
    }
    CP_WAIT1();
    __syncthreads();

    for (int it = 0; it < K16; it++) {
        const int buf = it % GSTAGES;

        if (it + GSTAGES - 1 < K16) {
            const int s = (it + GSTAGES - 1) % GSTAGES;
            const size_t base = (size_t)(it + GSTAGES - 1) * 512;
#pragma unroll
            for (int j = 0; j < 4; j++) {
                uint32_t sa = (uint32_t)__cvta_generic_to_shared(&As[s][tid + j * 128]);
                uint32_t sb = (uint32_t)__cvta_generic_to_shared(&Bs[s][tid + j * 128]);
                CP_ASYNC16(sa, ab + base + j * 128);
                CP_ASYNC16(sb, bb + base + j * 128);
            }
        }
        CP_COMMIT();

        const unsigned* Au = (const unsigned*)As[buf];
        const unsigned* Bu = (const unsigned*)Bs[buf];
#pragma unroll
        for (int ks = 0; ks < 2; ks++) {
            uint4 af[4];
            uint2 bf[8];
#pragma unroll
            for (int mt = 0; mt < 4; mt++)
                af[mt] = *(const uint4*)&Au[(ks * 8 + wm * 4 + mt) * 128 + lane * 4];
#pragma unroll
            for (int nt = 0; nt < 8; nt++)
                bf[nt] = *(const uint2*)&Bu[(ks * 16 + wn * 8 + nt) * 64 + lane * 2];
#pragma unroll
            for (int mt = 0; mt < 4; mt++)
#pragma unroll
                for (int nt = 0; nt < 8; nt++)
                    mma_tf32(acc[mt][nt], af[mt], bf[nt]);
        }

        CP_WAIT1();
        __syncthreads();
    }

    const int r_base = blockIdx.y * 128 + wm * 64 + (lane >> 2);
    const int c_base = blockIdx.x * 128 + wn * 64 + (lane & 3) * 2;
#pragma unroll
    for (int mt = 0; mt < 4; mt++) {
#pragma unroll
        for (int nt = 0; nt < 8; nt++) {
            int r = r_base + mt * 16;
            int c = c_base + nt * 8;
            *(float2*)&C[(size_t)r * N + c] =
                make_float2(acc[mt][nt][0], acc[mt][nt][1]);
            *(float2*)&C[(size_t)(r + 8) * N + c] =
                make_float2(acc[mt][nt][2], acc[mt][nt][3]);
        }
    }
}

// ---------------------------------------------------------------------------
// Tensor-core flash attention (prefix-LM mask). 256 queries/block, 32/warp.
// K/V tiles arrive pre-converted in fragment layout: fill = pure cp.async copy.
// Epilogue writes O directly in A-frag layout for GEMM3.
// ---------------------------------------------------------------------------
#define AT_TQ 256
#define AT_TK 64

__global__ __launch_bounds__(256, 1)
void attn_mma_kernel(const float* __restrict__ qkv,
                     const uint4* __restrict__ kfrag,
                     const uint4* __restrict__ vfrag,
                     unsigned* __restrict__ outf) {
    __shared__ unsigned Ks[8][8][32][2];  // 16KB
    __shared__ unsigned Vs[8][8][8][8];   // 16KB

    const int b = blockIdx.z;
    const int h = blockIdx.y;
    const int q0 = blockIdx.x * AT_TQ;
    const int tid = threadIdx.x;
    const int warp = tid >> 5;
    const int lane = tid & 31;

    const int P = g_prefix[b];

    const int q0w = q0 + warp * 32;
    const int qa = q0w + (lane >> 2);
    const int qc = qa + 16;
    const int e0 = (qa < P) ? P : (qa + 1);
    const int e1 = (qa + 8 < P) ? P : (qa + 9);
    const int e2 = (qc < P) ? P : (qc + 1);
    const int e3 = (qc + 8 < P) ? P : (qc + 9);
    const int min_end_w = (q0w < P) ? P : (q0w + 1);

    int kend_w = q0w + 32;
    if (P > kend_w) kend_w = P;
    if (kend_w > T_SZ) kend_w = T_SZ;
    int kend = q0 + AT_TQ;
    if (P > kend) kend = P;
    if (kend > T_SZ) kend = T_SZ;

    const float qscale = 0.125f * 1.4426950408889634f;
    uint4 aq[8][2];
    {
        const int c = lane & 3;
        const float* q0p = qkv + (size_t)(b * T_SZ + qa) * D3 + h * DK_SZ;
        const float* q1p = q0p + (size_t)8 * D3;
        const float* q2p = q0p + (size_t)16 * D3;
        const float* q3p = q0p + (size_t)24 * D3;
#pragma unroll
        for (int g = 0; g < 8; g++) {
            aq[g][0].x = f2tf32(q0p[g * 8 + c] * qscale);
            aq[g][0].y = f2tf32(q1p[g * 8 + c] * qscale);
            aq[g][0].z = f2tf32(q0p[g * 8 + c + 4] * qscale);
            aq[g][0].w = f2tf32(q1p[g * 8 + c + 4] * qscale);
            aq[g][1].x = f2tf32(q2p[g * 8 + c] * qscale);
            aq[g][1].y = f2tf32(q3p[g * 8 + c] * qscale);
            aq[g][1].z = f2tf32(q2p[g * 8 + c + 4] * qscale);
            aq[g][1].w = f2tf32(q3p[g * 8 + c + 4] * qscale);
        }
    }

    const uint4* kb = kfrag + (size_t)((b * H_SZ + h) * 32) * 1024;
    const uint4* vb = vfrag + (size_t)((b * H_SZ + h) * 32) * 1024;
    const uint32_t ksm = (uint32_t)__cvta_generic_to_shared(&Ks[0][0][0][0]);
    const uint32_t vsm = (uint32_t)__cvta_generic_to_shared(&Vs[0][0][0][0]);

    float oacc[2][8][4];
#pragma unroll
    for (int mf = 0; mf < 2; mf++)
#pragma unroll
        for (int dt = 0; dt < 8; dt++)
#pragma unroll
            for (int e = 0; e < 4; e++) oacc[mf][dt][e] = 0.0f;
    float m0 = -1e30f, m1 = -1e30f, m2 = -1e30f, m3 = -1e30f;
    float l0 = 0.0f, l1 = 0.0f, l2 = 0.0f, l3 = 0.0f;

    for (int kt = 0; kt < kend; kt += AT_TK) {
        // ---- tile fill: pure fragment copy (4+4 cp.async per thread)
        {
            const size_t tb = (size_t)(kt >> 6) * 1024;
#pragma unroll
            for (int j = 0; j < 4; j++) {
                CP_ASYNC16(ksm + (tid + j * 256) * 16, kb + tb + tid + j * 256);
                CP_ASYNC16(vsm + (tid + j * 256) * 16, vb + tb + tid + j * 256);
            }
            CP_COMMIT();
            CP_WAIT0();
        }
        __syncthreads();

        if (kt < kend_w) {
            float sacc[2][8][4];
#pragma unroll
            for (int mf = 0; mf < 2; mf++)
#pragma unroll
                for (int nt = 0; nt < 8; nt++)
#pragma unroll
                    for (int e = 0; e < 4; e++) sacc[mf][nt][e] = 0.0f;

#pragma unroll
            for (int nt = 0; nt < 8; nt++) {
                if (kt + nt * 8 < kend_w) {
#pragma unroll
                    for (int g = 0; g < 8; g++) {
                        uint2 bf = *(const uint2*)&Ks[g][nt][lane][0];
                        mma_tf32(sacc[0][nt], aq[g][0], bf);
                        mma_tf32(sacc[1][nt], aq[g][1], bf);
                    }
                }
            }

            if (kt + AT_TK > min_end_w) {
#pragma unroll
                for (int nt = 0; nt < 8; nt++) {
                    int k0 = kt + nt * 8 + (lane & 3) * 2;
                    if (k0 >= e0)     sacc[0][nt][0] = -1e30f;
                    if (k0 + 1 >= e0) sacc[0][nt][1] = -1e30f;
                    if (k0 >= e1)     sacc[0][nt][2] = -1e30f;
                    if (k0 + 1 >= e1) sacc[0][nt][3] = -1e30f;
                    if (k0 >= e2)     sacc[1][nt][0] = -1e30f;
                    if (k0 + 1 >= e2) sacc[1][nt][1] = -1e30f;
                    if (k0 >= e3)     sacc[1][nt][2] = -1e30f;
                    if (k0 + 1 >= e3) sacc[1][nt][3] = -1e30f;
                }
            }

            float tm0 = -1e30f, tm1 = -1e30f, tm2 = -1e30f, tm3 = -1e30f;
#pragma unroll
            for (int nt = 0; nt < 8; nt++) {
                tm0 = fmaxf(tm0, fmaxf(sacc[0][nt][0], sacc[0][nt][1]));
                tm1 = fmaxf(tm1, fmaxf(sacc[0][nt][2], sacc[0][nt][3]));
                tm2 = fmaxf(tm2, fmaxf(sacc[1][nt][0], sacc[1][nt][1]));
                tm3 = fmaxf(tm3, fmaxf(sacc[1][nt][2], sacc[1][nt][3]));
            }
            tm0 = fmaxf(tm0, __shfl_xor_sync(0xffffffffu, tm0, 1));
            tm0 = fmaxf(tm0, __shfl_xor_sync(0xffffffffu, tm0, 2));
            tm1 = fmaxf(tm1, __shfl_xor_sync(0xffffffffu, tm1, 1));
            tm1 = fmaxf(tm1, __shfl_xor_sync(0xffffffffu, tm1, 2));
            tm2 = fmaxf(tm2, __shfl_xor_sync(0xffffffffu, tm2, 1));
            tm2 = fmaxf(tm2, __shfl_xor_sync(0xffffffffu, tm2, 2));
            tm3 = fmaxf(tm3, __shfl_xor_sync(0xffffffffu, tm3, 1));
            tm3 = fmaxf(tm3, __shfl_xor_sync(0xffffffffu, tm3, 2));

            float mn0 = fmaxf(m0, tm0), mn1 = fmaxf(m1, tm1);
            float mn2 = fmaxf(m2, tm2), mn3 = fmaxf(m3, tm3);
            float c0 = ex2(m0 - mn0), c1 = ex2(m1 - mn1);
            float c2 = ex2(m2 - mn2), c3 = ex2(m3 - mn3);
            m0 = mn0; m1 = mn1; m2 = mn2; m3 = mn3;

#pragma unroll
            for (int dt = 0; dt < 8; dt++) {
                oacc[0][dt][0] *= c0; oacc[0][dt][1] *= c0;
                oacc[0][dt][2] *= c1; oacc[0][dt][3] *= c1;
                oacc[1][dt][0] *= c2; oacc[1][dt][1] *= c2;
                oacc[1][dt][2] *= c3; oacc[1][dt][3] *= c3;
            }

            float ts0 = 0.0f, ts1 = 0.0f, ts2 = 0.0f, ts3 = 0.0f;
#pragma unroll
            for (int g = 0; g < 8; g++) {
                if (kt + g * 8 < kend_w) {
                    float p00 = ex2(sacc[0][g][0] - mn0);
                    float p01 = ex2(sacc[0][g][1] - mn0);
                    float p02 = ex2(sacc[0][g][2] - mn1);
                    float p03 = ex2(sacc[0][g][3] - mn1);
                    float p10 = ex2(sacc[1][g][0] - mn2);
                    float p11 = ex2(sacc[1][g][1] - mn2);
                    float p12 = ex2(sacc[1][g][2] - mn3);
                    float p13 = ex2(sacc[1][g][3] - mn3);
                    ts0 += p00 + p01; ts1 += p02 + p03;
                    ts2 += p10 + p11; ts3 += p12 + p13;
                    uint4 ap0 = make_uint4(f2tf32(p00), f2tf32(p02), f2tf32(p01), f2tf32(p03));
                    uint4 ap1 = make_uint4(f2tf32(p10), f2tf32(p12), f2tf32(p11), f2tf32(p13));
#pragma unroll
                    for (int dt = 0; dt < 8; dt++) {
                        uint2 vf = *(const uint2*)&Vs[g][dt][(lane >> 2) ^ g][2 * (lane & 3)];
                        mma_tf32(oacc[0][dt], ap0, vf);
                        mma_tf32(oacc[1][dt], ap1, vf);
                    }
                }
            }
            ts0 += __shfl_xor_sync(0xffffffffu, ts0, 1);
            ts0 += __shfl_xor_sync(0xffffffffu, ts0, 2);
            ts1 += __shfl_xor_sync(0xffffffffu, ts1, 1);
            ts1 += __shfl_xor_sync(0xffffffffu, ts1, 2);
            ts2 += __shfl_xor_sync(0xffffffffu, ts2, 1);
            ts2 += __shfl_xor_sync(0xffffffffu, ts2, 2);
            ts3 += __shfl_xor_sync(0xffffffffu, ts3, 1);
            ts3 += __shfl_xor_sync(0xffffffffu, ts3, 2);
            l0 = l0 * c0 + ts0;
            l1 = l1 * c1 + ts1;
            l2 = l2 * c2 + ts2;
            l3 = l3 * c3 + ts3;
        }
        __syncthreads();
    }

    // epilogue: scatter into A-frag layout for GEMM3
    const float i0 = 1.0f / l0, i1 = 1.0f / l1, i2 = 1.0f / l2, i3 = 1.0f / l3;
    const int mb = b * T_SZ;
    const int col0 = h * DK_SZ + (lane & 3) * 2;
#pragma unroll
    for (int dt = 0; dt < 8; dt++) {
        int c = col0 + dt * 8;
        st_frag(outf, mb + qa,      c,     oacc[0][dt][0] * i0);
        st_frag(outf, mb + qa,      c + 1, oacc[0][dt][1] * i0);
        st_frag(outf, mb + qa + 8,  c,     oacc[0][dt][2] * i1);
        st_frag(outf, mb + qa + 8,  c + 1, oacc[0][dt][3] * i1);
        st_frag(outf, mb + qa + 16, c,     oacc[1][dt][0] * i2);
        st_frag(outf, mb + qa + 16, c + 1, oacc[1][dt][1] * i2);
        st_frag(outf, mb + qa + 24, c,     oacc[1][dt][2] * i3);
        st_frag(outf, mb + qa + 24, c + 1, oacc[1][dt][3] * i3);
    }
}

// ---------------------------------------------------------------------------
// launch
// ---------------------------------------------------------------------------
extern "C" void kernel_launch(void* const* d_in, const int* in_sizes, int n_in,
                              void* d_out, int out_size) {
    const float* x = (const float*)d_in[0];
    const int* prefix_raw = (const int*)d_in[1];
    const float* W_qkv = (const float*)d_in[2];
    const float* W_o = (const float*)d_in[3];
    float* out = (float*)d_out;

    float* qkv = nullptr;
    unsigned *xf = nullptr, *wqf = nullptr, *wof = nullptr, *af = nullptr;
    unsigned *kf = nullptr, *vf = nullptr;
    cudaGetSymbolAddress((void**)&qkv, g_qkv);
    cudaGetSymbolAddress((void**)&xf, g_xfrag);
    cudaGetSymbolAddress((void**)&wqf, g_wqkvfrag);
    cudaGetSymbolAddress((void**)&wof, g_wofrag);
    cudaGetSymbolAddress((void**)&af, g_attnfrag);
    cudaGetSymbolAddress((void**)&kf, g_kfrag);
    cudaGetSymbolAddress((void**)&vf, g_vfrag);

    const int M = B_SZ * T_SZ;  // 8192

    decode_prefix_kernel<<<1, 1>>>(prefix_raw);

    // 0) operand prep into fragment layouts
    {
        int nx = M * D_SZ / 4;
        prep_afrag<<<nx / 256, 256>>>(x, (uint4*)xf, D_SZ, nx);
        int nq = D3 * D_SZ / 4;
        prep_bfrag<<<nq / 256, 256>>>(W_qkv, (uint4*)wqf, D_SZ, nq);
        int no = D_SZ * D_SZ / 4;
        prep_bfrag<<<no / 256, 256>>>(W_o, (uint4*)wof, D_SZ, no);
    }

    // 1) qkv = x @ W_qkv^T   [8192, 3072]
    {
        dim3 grid(D3 / 128, M / 128);
        gemm_frag_nt<<<grid, 128>>>((const uint4*)xf, (const uint4*)wqf, qkv, M, D3, D_SZ);
    }

    // 1b) K/V -> attention fragment layouts
    {
        int nkv = B_SZ * H_SZ * 32 * 1024;   // 2,097,152 quads each
        prep_kfrag<<<nkv / 256, 256>>>(qkv, (uint4*)kf, nkv);
        prep_vfrag<<<nkv / 256, 256>>>(qkv, (uint4*)vf, nkv);
    }

    // 2) attention -> g_attnfrag (A-frag layout)
    {
        dim3 grid(T_SZ / AT_TQ, H_SZ, B_SZ);
        attn_mma_kernel<<<grid, 256>>>(qkv, (const uint4*)kf, (const uint4*)vf, af);
    }

    // 3) out = attn @ W_o^T  [8192, 1024]
    {
        dim3 grid(D_SZ / 128, M / 128);
        gemm_frag_nt<<<grid, 128>>>((const uint4*)af, (const uint4*)wof, out, M, D_SZ, D_SZ);
    }
}